// round 1
// baseline (speedup 1.0000x reference)
#include <cuda_runtime.h>
#include <cuda_bf16.h>
#include <math.h>

// Problem constants
#define BB 2
#define SS 2048
#define DD 1024
#define HH 16
#define DH 64
#define MM (BB * SS)          // 4096 rows
#define FF (4 * DD)           // 4096 ffn hidden
#define EPS 1e-5f

// ---------------------------------------------------------------------------
// Scratch (static device memory — allocation-free)
// ---------------------------------------------------------------------------
__device__ float g_q[MM * DD];
__device__ float g_k[MM * DD];
__device__ float g_v[MM * DD];
__device__ float g_z[MM * DD];
__device__ float g_t[MM * DD];   // LN inputs (reused)
__device__ float g_o1[MM * DD];  // LN1 output (residual for block 2)
__device__ float g_h[MM * FF];   // ffn hidden

// ---------------------------------------------------------------------------
// SGEMM: C[M,N] = A[M,K] @ B[N,K]^T + bias[N] (+res) (ReLU)
// 128x128 tile, K-tile 8, 256 threads, 8x8 per thread. M%128==N%128==0, K%8==0.
// ---------------------------------------------------------------------------
template <int RELU, int RES>
__global__ __launch_bounds__(256) void sgemm_kernel(
    const float* __restrict__ A, const float* __restrict__ B,
    const float* __restrict__ bias, const float* __restrict__ res,
    float* __restrict__ C, int M, int N, int K)
{
    __shared__ float As[8][128];
    __shared__ float Bs[8][128];

    const int tid = threadIdx.x;
    const int tx = tid & 15;        // col group
    const int ty = tid >> 4;        // row group
    const int bm = blockIdx.y * 128;
    const int bn = blockIdx.x * 128;

    const int lrow = tid >> 1;          // 0..127
    const int lcol = (tid & 1) * 4;     // 0 or 4
    const float* Ap = A + (size_t)(bm + lrow) * K + lcol;
    const float* Bp = B + (size_t)(bn + lrow) * K + lcol;

    float acc[8][8];
#pragma unroll
    for (int i = 0; i < 8; i++)
#pragma unroll
        for (int j = 0; j < 8; j++) acc[i][j] = 0.f;

    for (int k0 = 0; k0 < K; k0 += 8) {
        float4 av = *(const float4*)(Ap + k0);
        float4 bv = *(const float4*)(Bp + k0);
        __syncthreads();
        As[lcol + 0][lrow] = av.x;
        As[lcol + 1][lrow] = av.y;
        As[lcol + 2][lrow] = av.z;
        As[lcol + 3][lrow] = av.w;
        Bs[lcol + 0][lrow] = bv.x;
        Bs[lcol + 1][lrow] = bv.y;
        Bs[lcol + 2][lrow] = bv.z;
        Bs[lcol + 3][lrow] = bv.w;
        __syncthreads();
#pragma unroll
        for (int kk = 0; kk < 8; kk++) {
            float4 a0 = *(const float4*)(&As[kk][ty * 8]);
            float4 a1 = *(const float4*)(&As[kk][ty * 8 + 4]);
            float4 b0 = *(const float4*)(&Bs[kk][tx * 8]);
            float4 b1 = *(const float4*)(&Bs[kk][tx * 8 + 4]);
            float ar[8] = {a0.x, a0.y, a0.z, a0.w, a1.x, a1.y, a1.z, a1.w};
            float br[8] = {b0.x, b0.y, b0.z, b0.w, b1.x, b1.y, b1.z, b1.w};
#pragma unroll
            for (int i = 0; i < 8; i++)
#pragma unroll
                for (int j = 0; j < 8; j++) acc[i][j] = fmaf(ar[i], br[j], acc[i][j]);
        }
    }

    // epilogue
#pragma unroll
    for (int i = 0; i < 8; i++) {
        const int row = bm + ty * 8 + i;
#pragma unroll
        for (int jv = 0; jv < 2; jv++) {
            const int col = bn + tx * 8 + jv * 4;
            const size_t idx = (size_t)row * N + col;
            float4 bia = *(const float4*)(bias + col);
            float o0 = acc[i][jv * 4 + 0] + bia.x;
            float o1 = acc[i][jv * 4 + 1] + bia.y;
            float o2 = acc[i][jv * 4 + 2] + bia.z;
            float o3 = acc[i][jv * 4 + 3] + bia.w;
            if (RELU) {
                o0 = fmaxf(o0, 0.f); o1 = fmaxf(o1, 0.f);
                o2 = fmaxf(o2, 0.f); o3 = fmaxf(o3, 0.f);
            }
            if (RES) {
                float4 rr = *(const float4*)(res + idx);
                o0 += rr.x; o1 += rr.y; o2 += rr.z; o3 += rr.w;
            }
            *(float4*)(C + idx) = make_float4(o0, o1, o2, o3);
        }
    }
}

// ---------------------------------------------------------------------------
// Flash attention (fp32): per (b,h), BQ=64 query tile, BK=64 key tile,
// online softmax. Q/K stored feature-major (transposed) in smem so the
// inner loops are all float4 LDS. Output written directly in concat-head
// layout O[b, s, h*64 + e], scaled by 1/(l * sqrt(64)).
// ---------------------------------------------------------------------------
#define ATTN_SMEM ((4 * 64 * 68 + 3 * 64) * 4)

__global__ __launch_bounds__(256) void attn_kernel(
    const float* __restrict__ Q, const float* __restrict__ K,
    const float* __restrict__ V, float* __restrict__ O)
{
    extern __shared__ float sm[];
    float* Qt = sm;                 // [64 feat][68] : Qt[c][r]
    float* Kt = Qt + 64 * 68;       // [64 feat][68] : Kt[c][r]
    float* Vs = Kt + 64 * 68;       // [64 key][68]  : Vs[k][c]
    float* St = Vs + 64 * 68;       // [64 key][68]  : St[k][q]
    float* mrow = St + 64 * 68;     // [64]
    float* lrow = mrow + 64;        // [64]
    float* srow = lrow + 64;        // [64]

    const int tid = threadIdx.x;
    const int tx = tid & 15;
    const int ty = tid >> 4;
    const int b = blockIdx.z;
    const int h = blockIdx.y;
    const int qb = blockIdx.x * 64;
    const size_t base = ((size_t)b * SS) * DD + (size_t)h * DH;

    // load Q tile transposed
    {
        const int r0 = tid >> 4;
        const int c4 = (tid & 15) * 4;
        for (int r = r0; r < 64; r += 16) {
            float4 qv = *(const float4*)(Q + base + (size_t)(qb + r) * DD + c4);
            Qt[(c4 + 0) * 68 + r] = qv.x;
            Qt[(c4 + 1) * 68 + r] = qv.y;
            Qt[(c4 + 2) * 68 + r] = qv.z;
            Qt[(c4 + 3) * 68 + r] = qv.w;
        }
    }
    if (tid < 64) { mrow[tid] = -1e30f; lrow[tid] = 0.f; }

    float acc[4][4] = {};

    for (int kb = 0; kb < SS; kb += 64) {
        __syncthreads();
        // load K (transposed) and V (row-major) tiles
        {
            const int r0 = tid >> 4;
            const int c4 = (tid & 15) * 4;
            for (int r = r0; r < 64; r += 16) {
                float4 kv = *(const float4*)(K + base + (size_t)(kb + r) * DD + c4);
                Kt[(c4 + 0) * 68 + r] = kv.x;
                Kt[(c4 + 1) * 68 + r] = kv.y;
                Kt[(c4 + 2) * 68 + r] = kv.z;
                Kt[(c4 + 3) * 68 + r] = kv.w;
                float4 vv = *(const float4*)(V + base + (size_t)(kb + r) * DD + c4);
                *(float4*)(Vs + r * 68 + c4) = vv;
            }
        }
        __syncthreads();

        // S tile: s[i][j] = sum_c Q[qb+ty*4+i][c] * K[kb+tx*4+j][c]
        float s[4][4] = {};
#pragma unroll 8
        for (int c = 0; c < 64; c++) {
            float4 a = *(const float4*)(Qt + c * 68 + ty * 4);
            float4 bb = *(const float4*)(Kt + c * 68 + tx * 4);
            float ar[4] = {a.x, a.y, a.z, a.w};
            float br[4] = {bb.x, bb.y, bb.z, bb.w};
#pragma unroll
            for (int i = 0; i < 4; i++)
#pragma unroll
                for (int j = 0; j < 4; j++) s[i][j] = fmaf(ar[i], br[j], s[i][j]);
        }
        // store transposed: St[key][query]
#pragma unroll
        for (int j = 0; j < 4; j++) {
            *(float4*)(St + (tx * 4 + j) * 68 + ty * 4) =
                make_float4(s[0][j], s[1][j], s[2][j], s[3][j]);
        }
        __syncthreads();

        // online softmax: one thread per query row
        if (tid < 64) {
            const int r = tid;
            float m_old = mrow[r];
            float mx = m_old;
            for (int c = 0; c < 64; c++) mx = fmaxf(mx, St[c * 68 + r]);
            float scale = __expf(m_old - mx);
            float sum = 0.f;
            for (int c = 0; c < 64; c++) {
                float p = __expf(St[c * 68 + r] - mx);
                St[c * 68 + r] = p;
                sum += p;
            }
            lrow[r] = lrow[r] * scale + sum;
            mrow[r] = mx;
            srow[r] = scale;
        }
        __syncthreads();

        // rescale + accumulate O += P @ V
        float sc[4];
#pragma unroll
        for (int i = 0; i < 4; i++) sc[i] = srow[ty * 4 + i];
#pragma unroll
        for (int i = 0; i < 4; i++)
#pragma unroll
            for (int j = 0; j < 4; j++) acc[i][j] *= sc[i];
#pragma unroll 8
        for (int kk = 0; kk < 64; kk++) {
            float4 p = *(const float4*)(St + kk * 68 + ty * 4);
            float4 vv = *(const float4*)(Vs + kk * 68 + tx * 4);
            float pr[4] = {p.x, p.y, p.z, p.w};
            float vr[4] = {vv.x, vv.y, vv.z, vv.w};
#pragma unroll
            for (int i = 0; i < 4; i++)
#pragma unroll
                for (int j = 0; j < 4; j++) acc[i][j] = fmaf(pr[i], vr[j], acc[i][j]);
        }
    }

    // write: O[b, qb+r, h*64 + c] = acc / (l * sqrt(64))
#pragma unroll
    for (int i = 0; i < 4; i++) {
        const int r = ty * 4 + i;
        const float invl = 0.125f / lrow[r];
        *(float4*)(O + base + (size_t)(qb + r) * DD + tx * 4) =
            make_float4(acc[i][0] * invl, acc[i][1] * invl,
                        acc[i][2] * invl, acc[i][3] * invl);
    }
}

// ---------------------------------------------------------------------------
// LayerNorm over D=1024, one block per row (residual already folded into x)
// ---------------------------------------------------------------------------
__global__ __launch_bounds__(256) void ln_kernel(
    const float* __restrict__ x, const float* __restrict__ g,
    const float* __restrict__ be, float* __restrict__ out)
{
    const int row = blockIdx.x;
    const int tid = threadIdx.x;
    const float* xr = x + (size_t)row * DD;

    float4 xv = *(const float4*)(xr + tid * 4);
    float sum = xv.x + xv.y + xv.z + xv.w;
    float sq = xv.x * xv.x + xv.y * xv.y + xv.z * xv.z + xv.w * xv.w;

    __shared__ float s1[32], s2[32];
#pragma unroll
    for (int o = 16; o > 0; o >>= 1) {
        sum += __shfl_xor_sync(0xffffffffu, sum, o);
        sq += __shfl_xor_sync(0xffffffffu, sq, o);
    }
    const int w = tid >> 5, l = tid & 31;
    if (l == 0) { s1[w] = sum; s2[w] = sq; }
    __syncthreads();
    if (w == 0) {
        sum = (l < 8) ? s1[l] : 0.f;
        sq = (l < 8) ? s2[l] : 0.f;
#pragma unroll
        for (int o = 4; o > 0; o >>= 1) {
            sum += __shfl_xor_sync(0xffffffffu, sum, o);
            sq += __shfl_xor_sync(0xffffffffu, sq, o);
        }
        if (l == 0) { s1[0] = sum; s2[0] = sq; }
    }
    __syncthreads();
    const float mu = s1[0] * (1.f / DD);
    const float var = s2[0] * (1.f / DD) - mu * mu;
    const float rstd = rsqrtf(var + EPS);

    float4 gv = *(const float4*)(g + tid * 4);
    float4 bv = *(const float4*)(be + tid * 4);
    float4 ov;
    ov.x = (xv.x - mu) * rstd * gv.x + bv.x;
    ov.y = (xv.y - mu) * rstd * gv.y + bv.y;
    ov.z = (xv.z - mu) * rstd * gv.z + bv.z;
    ov.w = (xv.w - mu) * rstd * gv.w + bv.w;
    *(float4*)(out + (size_t)row * DD + tid * 4) = ov;
}

// ---------------------------------------------------------------------------
// Launch
// ---------------------------------------------------------------------------
extern "C" void kernel_launch(void* const* d_in, const int* in_sizes, int n_in,
                              void* d_out, int out_size)
{
    const float* emb = (const float*)d_in[0];
    const float* Wq  = (const float*)d_in[1];
    const float* bq  = (const float*)d_in[2];
    const float* Wk  = (const float*)d_in[3];
    const float* bk  = (const float*)d_in[4];
    const float* Wv  = (const float*)d_in[5];
    const float* bv  = (const float*)d_in[6];
    const float* W0  = (const float*)d_in[7];
    const float* b0  = (const float*)d_in[8];
    const float* g1  = (const float*)d_in[9];
    const float* be1 = (const float*)d_in[10];
    const float* W1  = (const float*)d_in[11];
    const float* b1  = (const float*)d_in[12];
    const float* W2  = (const float*)d_in[13];
    const float* b2  = (const float*)d_in[14];
    const float* g2  = (const float*)d_in[15];
    const float* be2 = (const float*)d_in[16];
    float* out = (float*)d_out;

    float *q, *k, *v, *z, *t, *o1, *hb;
    cudaGetSymbolAddress((void**)&q, g_q);
    cudaGetSymbolAddress((void**)&k, g_k);
    cudaGetSymbolAddress((void**)&v, g_v);
    cudaGetSymbolAddress((void**)&z, g_z);
    cudaGetSymbolAddress((void**)&t, g_t);
    cudaGetSymbolAddress((void**)&o1, g_o1);
    cudaGetSymbolAddress((void**)&hb, g_h);

    cudaFuncSetAttribute(attn_kernel,
                         cudaFuncAttributeMaxDynamicSharedMemorySize, ATTN_SMEM);

    const dim3 blk(256);
    const dim3 gD(DD / 128, MM / 128);   // N=1024 outputs
    const dim3 gF(FF / 128, MM / 128);   // N=4096 outputs

    // QKV projections
    sgemm_kernel<0, 0><<<gD, blk>>>(emb, Wq, bq, nullptr, q, MM, DD, DD);
    sgemm_kernel<0, 0><<<gD, blk>>>(emb, Wk, bk, nullptr, k, MM, DD, DD);
    sgemm_kernel<0, 0><<<gD, blk>>>(emb, Wv, bv, nullptr, v, MM, DD, DD);

    // attention -> z (concat-head layout)
    attn_kernel<<<dim3(SS / 64, HH, BB), blk, ATTN_SMEM>>>(q, k, v, z);

    // W0 projection + residual(emb), then LN1 -> o1
    sgemm_kernel<0, 1><<<gD, blk>>>(z, W0, b0, emb, t, MM, DD, DD);
    ln_kernel<<<MM, blk>>>(t, g1, be1, o1);

    // FFN
    sgemm_kernel<1, 0><<<gF, blk>>>(o1, W1, b1, nullptr, hb, MM, FF, DD);
    sgemm_kernel<0, 1><<<gD, blk>>>(hb, W2, b2, o1, t, MM, DD, FF);
    ln_kernel<<<MM, blk>>>(t, g2, be2, out);
}

// round 3
// speedup vs baseline: 2.0408x; 2.0408x over previous
#include <cuda_runtime.h>
#include <cuda_bf16.h>
#include <math.h>
#include <stdint.h>

// Problem constants
#define BB 2
#define SS 2048
#define DD 1024
#define HH 16
#define DH 64
#define MM (BB * SS)          // 4096 rows
#define FF (4 * DD)           // 4096 ffn hidden
#define EPS 1e-5f

// ---------------------------------------------------------------------------
// Scratch (static device memory — allocation-free)
// ---------------------------------------------------------------------------
__device__ float g_q[MM * DD];
__device__ float g_k[MM * DD];
__device__ float g_v[MM * DD];
__device__ float g_z[MM * DD];     // attn out
__device__ float g_t[MM * DD];     // LN inputs (reused)
__device__ float g_o1[MM * DD];    // LN1 output (residual + A of FFN)
__device__ float g_h[MM * FF];     // ffn hidden

// ---------------------------------------------------------------------------
// Helpers
// ---------------------------------------------------------------------------
__device__ __forceinline__ uint32_t tf32u(float x) {
    uint32_t u = __float_as_uint(x), r;
    asm("cvt.rna.tf32.f32 %0, %1;" : "=r"(r) : "r"(u));
    return r;
}
__device__ __forceinline__ uint32_t su32(const void* p) {
    return (uint32_t)__cvta_generic_to_shared(p);
}
__device__ __forceinline__ void ldsm_x4(uint32_t* r, uint32_t addr) {
    asm volatile("ldmatrix.sync.aligned.m8n8.x4.shared.b16 {%0,%1,%2,%3}, [%4];"
                 : "=r"(r[0]), "=r"(r[1]), "=r"(r[2]), "=r"(r[3]) : "r"(addr));
}
__device__ __forceinline__ void mma_tf32(float* d, const uint32_t* a,
                                         const uint32_t b0, const uint32_t b1) {
    asm volatile(
        "mma.sync.aligned.m16n8k8.row.col.f32.tf32.tf32.f32 "
        "{%0,%1,%2,%3}, {%4,%5,%6,%7}, {%8,%9}, {%0,%1,%2,%3};"
        : "+f"(d[0]), "+f"(d[1]), "+f"(d[2]), "+f"(d[3])
        : "r"(a[0]), "r"(a[1]), "r"(a[2]), "r"(a[3]), "r"(b0), "r"(b1));
}

// SW128 swizzle on byte offsets (rows of 128B): chunk' = chunk ^ (row%8)
#define SWZ(x) ((x) ^ (((x) >> 3) & 0x70))

// ---------------------------------------------------------------------------
// tf32 mma.sync GEMM: C[M,N] = A[M,K] @ B[N,K]^T + bias (+ReLU) (+res)
// CTA tile 128x128, K-tile 32 (two SW128 rows of 32 floats), double-buffered.
// 8 warps = 2(M) x 4(N); warp tile 64x32 = 4 m16-tiles x 4 n8-tiles.
// Operands rounded to tf32 (cvt.rna) during smem staging.
// ---------------------------------------------------------------------------
#define GSMEM 65536   // 2 buffers x (A 16KB + B 16KB)

template <int RELU, int RES>
__global__ __launch_bounds__(256) void tc_gemm(
    const float* __restrict__ A, const float* __restrict__ B,
    const float* __restrict__ bias, const float* __restrict__ res,
    float* __restrict__ C, int M, int N, int K)
{
    extern __shared__ __align__(1024) char smem[];
    const int tid = threadIdx.x;
    const int lane = tid & 31, wid = tid >> 5;
    const int bm = blockIdx.y * 128, bn = blockIdx.x * 128;

    // warp position in CTA tile
    const int wm = (wid >> 2) * 64;      // 0 or 64
    const int wn = (wid & 3) * 32;       // 0,32,64,96

    // ldmatrix lane roles
    const int q = lane >> 3, r8 = lane & 7;
    const int ha = q >> 1;               // A: k-half from q>>1, row+8 from q&1
    const int hb = q & 1;                // B: k-half from q&1,  row+8 from q>>1

    const uint32_t sbase = su32(smem);
    // per-lane row base addresses (byte) within a 16KB tile, for each buffer
    // A matrix rows: wm + m*16 + (q&1)*8 + r8
    uint32_t aRow[4], bRow[2];
#pragma unroll
    for (int m = 0; m < 4; m++)
        aRow[m] = (uint32_t)((wm + m * 16 + (q & 1) * 8 + r8) * 128);
#pragma unroll
    for (int p = 0; p < 2; p++)
        bRow[p] = (uint32_t)((wn + p * 16 + (q >> 1) * 8 + r8) * 128);

    // staging indices: thread stages 4 x 16B for A and B per K-tile
    const int srow = tid >> 1;                  // unused pattern below uses c
    (void)srow;

    float acc[4][4][4];
#pragma unroll
    for (int m = 0; m < 4; m++)
#pragma unroll
        for (int n = 0; n < 4; n++)
#pragma unroll
            for (int e = 0; e < 4; e++) acc[m][n][e] = 0.f;

    const int nk = K / 32;

    // ---- stage K-tile 0 into buffer 0 ----
    {
        char* sA = smem;
        char* sB = smem + 16384;
#pragma unroll
        for (int i = 0; i < 4; i++) {
            int c = i * 256 + tid, row = c >> 3, cc = c & 7;
            float4 a = *(const float4*)(A + (size_t)(bm + row) * K + cc * 4);
            float4 b = *(const float4*)(B + (size_t)(bn + row) * K + cc * 4);
            int off = SWZ(row * 128 + cc * 16);
            *(uint4*)(sA + off) = make_uint4(tf32u(a.x), tf32u(a.y), tf32u(a.z), tf32u(a.w));
            *(uint4*)(sB + off) = make_uint4(tf32u(b.x), tf32u(b.y), tf32u(b.z), tf32u(b.w));
        }
    }
    __syncthreads();

    for (int kt = 0; kt < nk; kt++) {
        // issue global loads for next K-tile early
        float4 ra[4], rb[4];
        if (kt + 1 < nk) {
#pragma unroll
            for (int i = 0; i < 4; i++) {
                int c = i * 256 + tid, row = c >> 3, cc = c & 7;
                ra[i] = *(const float4*)(A + (size_t)(bm + row) * K + (kt + 1) * 32 + cc * 4);
                rb[i] = *(const float4*)(B + (size_t)(bn + row) * K + (kt + 1) * 32 + cc * 4);
            }
        }

        // compute on buffer kt&1
        const uint32_t abase = sbase + (kt & 1) * 32768u;
        const uint32_t bbase = abase + 16384u;
#pragma unroll
        for (int s = 0; s < 4; s++) {
            const uint32_t ca = (uint32_t)((((s << 1) | ha) ^ r8) << 4);
            const uint32_t cb = (uint32_t)((((s << 1) | hb) ^ r8) << 4);
            uint32_t af[4][4], bf[2][4];
#pragma unroll
            for (int m = 0; m < 4; m++) ldsm_x4(af[m], abase + aRow[m] + ca);
#pragma unroll
            for (int p = 0; p < 2; p++) ldsm_x4(bf[p], bbase + bRow[p] + cb);
#pragma unroll
            for (int m = 0; m < 4; m++) {
#pragma unroll
                for (int nt = 0; nt < 4; nt++) {
                    const int p = nt >> 1, e = (nt & 1) * 2;
                    mma_tf32(acc[m][nt], af[m], bf[p][e], bf[p][e + 1]);
                }
            }
        }

        // stage next tile into the other buffer
        if (kt + 1 < nk) {
            char* sA = smem + ((kt + 1) & 1) * 32768;
            char* sB = sA + 16384;
#pragma unroll
            for (int i = 0; i < 4; i++) {
                int c = i * 256 + tid, row = c >> 3, cc = c & 7;
                int off = SWZ(row * 128 + cc * 16);
                *(uint4*)(sA + off) = make_uint4(tf32u(ra[i].x), tf32u(ra[i].y),
                                                 tf32u(ra[i].z), tf32u(ra[i].w));
                *(uint4*)(sB + off) = make_uint4(tf32u(rb[i].x), tf32u(rb[i].y),
                                                 tf32u(rb[i].z), tf32u(rb[i].w));
            }
        }
        __syncthreads();
    }

    // ---- epilogue ----
    const int gid = lane >> 2, tig = lane & 3;
#pragma unroll
    for (int m = 0; m < 4; m++) {
#pragma unroll
        for (int hf = 0; hf < 2; hf++) {
            const int row = bm + wm + m * 16 + gid + hf * 8;
#pragma unroll
            for (int nt = 0; nt < 4; nt++) {
                const int col = bn + wn + nt * 8 + tig * 2;
                const size_t idx = (size_t)row * N + col;
                float2 bi = *(const float2*)(bias + col);
                float o0 = acc[m][nt][hf * 2 + 0] + bi.x;
                float o1 = acc[m][nt][hf * 2 + 1] + bi.y;
                if (RELU) { o0 = fmaxf(o0, 0.f); o1 = fmaxf(o1, 0.f); }
                if (RES) {
                    float2 rr = *(const float2*)(res + idx);
                    o0 += rr.x; o1 += rr.y;
                }
                *(float2*)(C + idx) = make_float2(o0, o1);
            }
        }
    }
}

// ---------------------------------------------------------------------------
// Flash attention (fp32 SIMT) — same as R1 (known good)
// ---------------------------------------------------------------------------
#define ATTN_SMEM ((4 * 64 * 68 + 3 * 64) * 4)

__global__ __launch_bounds__(256) void attn_kernel(
    const float* __restrict__ Q, const float* __restrict__ K,
    const float* __restrict__ V, float* __restrict__ O)
{
    extern __shared__ float sm[];
    float* Qt = sm;
    float* Kt = Qt + 64 * 68;
    float* Vs = Kt + 64 * 68;
    float* St = Vs + 64 * 68;
    float* mrow = St + 64 * 68;
    float* lrow = mrow + 64;
    float* srow = lrow + 64;

    const int tid = threadIdx.x;
    const int tx = tid & 15;
    const int ty = tid >> 4;
    const int b = blockIdx.z;
    const int h = blockIdx.y;
    const int qb = blockIdx.x * 64;
    const size_t base = ((size_t)b * SS) * DD + (size_t)h * DH;

    {
        const int r0 = tid >> 4;
        const int c4 = (tid & 15) * 4;
        for (int r = r0; r < 64; r += 16) {
            float4 qv = *(const float4*)(Q + base + (size_t)(qb + r) * DD + c4);
            Qt[(c4 + 0) * 68 + r] = qv.x;
            Qt[(c4 + 1) * 68 + r] = qv.y;
            Qt[(c4 + 2) * 68 + r] = qv.z;
            Qt[(c4 + 3) * 68 + r] = qv.w;
        }
    }
    if (tid < 64) { mrow[tid] = -1e30f; lrow[tid] = 0.f; }

    float acc[4][4] = {};

    for (int kb = 0; kb < SS; kb += 64) {
        __syncthreads();
        {
            const int r0 = tid >> 4;
            const int c4 = (tid & 15) * 4;
            for (int r = r0; r < 64; r += 16) {
                float4 kv = *(const float4*)(K + base + (size_t)(kb + r) * DD + c4);
                Kt[(c4 + 0) * 68 + r] = kv.x;
                Kt[(c4 + 1) * 68 + r] = kv.y;
                Kt[(c4 + 2) * 68 + r] = kv.z;
                Kt[(c4 + 3) * 68 + r] = kv.w;
                float4 vv = *(const float4*)(V + base + (size_t)(kb + r) * DD + c4);
                *(float4*)(Vs + r * 68 + c4) = vv;
            }
        }
        __syncthreads();

        float s[4][4] = {};
#pragma unroll 8
        for (int c = 0; c < 64; c++) {
            float4 a = *(const float4*)(Qt + c * 68 + ty * 4);
            float4 bb = *(const float4*)(Kt + c * 68 + tx * 4);
            float ar[4] = {a.x, a.y, a.z, a.w};
            float br[4] = {bb.x, bb.y, bb.z, bb.w};
#pragma unroll
            for (int i = 0; i < 4; i++)
#pragma unroll
                for (int j = 0; j < 4; j++) s[i][j] = fmaf(ar[i], br[j], s[i][j]);
        }
#pragma unroll
        for (int j = 0; j < 4; j++) {
            *(float4*)(St + (tx * 4 + j) * 68 + ty * 4) =
                make_float4(s[0][j], s[1][j], s[2][j], s[3][j]);
        }
        __syncthreads();

        if (tid < 64) {
            const int r = tid;
            float m_old = mrow[r];
            float mx = m_old;
            for (int c = 0; c < 64; c++) mx = fmaxf(mx, St[c * 68 + r]);
            float scale = __expf(m_old - mx);
            float sum = 0.f;
            for (int c = 0; c < 64; c++) {
                float p = __expf(St[c * 68 + r] - mx);
                St[c * 68 + r] = p;
                sum += p;
            }
            lrow[r] = lrow[r] * scale + sum;
            mrow[r] = mx;
            srow[r] = scale;
        }
        __syncthreads();

        float sc[4];
#pragma unroll
        for (int i = 0; i < 4; i++) sc[i] = srow[ty * 4 + i];
#pragma unroll
        for (int i = 0; i < 4; i++)
#pragma unroll
            for (int j = 0; j < 4; j++) acc[i][j] *= sc[i];
#pragma unroll 8
        for (int kk = 0; kk < 64; kk++) {
            float4 p = *(const float4*)(St + kk * 68 + ty * 4);
            float4 vv = *(const float4*)(Vs + kk * 68 + tx * 4);
            float pr[4] = {p.x, p.y, p.z, p.w};
            float vr[4] = {vv.x, vv.y, vv.z, vv.w};
#pragma unroll
            for (int i = 0; i < 4; i++)
#pragma unroll
                for (int j = 0; j < 4; j++) acc[i][j] = fmaf(pr[i], vr[j], acc[i][j]);
        }
    }

#pragma unroll
    for (int i = 0; i < 4; i++) {
        const int r = ty * 4 + i;
        const float invl = 0.125f / lrow[r];
        *(float4*)(O + base + (size_t)(qb + r) * DD + tx * 4) =
            make_float4(acc[i][0] * invl, acc[i][1] * invl,
                        acc[i][2] * invl, acc[i][3] * invl);
    }
}

// ---------------------------------------------------------------------------
// LayerNorm over D=1024
// ---------------------------------------------------------------------------
__global__ __launch_bounds__(256) void ln_kernel(
    const float* __restrict__ x, const float* __restrict__ g,
    const float* __restrict__ be, float* __restrict__ out)
{
    const int row = blockIdx.x;
    const int tid = threadIdx.x;
    const float* xr = x + (size_t)row * DD;

    float4 xv = *(const float4*)(xr + tid * 4);
    float sum = xv.x + xv.y + xv.z + xv.w;
    float sq = xv.x * xv.x + xv.y * xv.y + xv.z * xv.z + xv.w * xv.w;

    __shared__ float s1[32], s2[32];
#pragma unroll
    for (int o = 16; o > 0; o >>= 1) {
        sum += __shfl_xor_sync(0xffffffffu, sum, o);
        sq += __shfl_xor_sync(0xffffffffu, sq, o);
    }
    const int w = tid >> 5, l = tid & 31;
    if (l == 0) { s1[w] = sum; s2[w] = sq; }
    __syncthreads();
    if (w == 0) {
        sum = (l < 8) ? s1[l] : 0.f;
        sq = (l < 8) ? s2[l] : 0.f;
#pragma unroll
        for (int o = 4; o > 0; o >>= 1) {
            sum += __shfl_xor_sync(0xffffffffu, sum, o);
            sq += __shfl_xor_sync(0xffffffffu, sq, o);
        }
        if (l == 0) { s1[0] = sum; s2[0] = sq; }
    }
    __syncthreads();
    const float mu = s1[0] * (1.f / DD);
    const float var = s2[0] * (1.f / DD) - mu * mu;
    const float rstd = rsqrtf(var + EPS);

    float4 gv = *(const float4*)(g + tid * 4);
    float4 bv = *(const float4*)(be + tid * 4);
    float4 ov;
    ov.x = (xv.x - mu) * rstd * gv.x + bv.x;
    ov.y = (xv.y - mu) * rstd * gv.y + bv.y;
    ov.z = (xv.z - mu) * rstd * gv.z + bv.z;
    ov.w = (xv.w - mu) * rstd * gv.w + bv.w;
    *(float4*)(out + (size_t)row * DD + tid * 4) = ov;
}

// ---------------------------------------------------------------------------
// Launch
// ---------------------------------------------------------------------------
extern "C" void kernel_launch(void* const* d_in, const int* in_sizes, int n_in,
                              void* d_out, int out_size)
{
    const float* emb = (const float*)d_in[0];
    const float* Wq  = (const float*)d_in[1];
    const float* bq  = (const float*)d_in[2];
    const float* Wk  = (const float*)d_in[3];
    const float* bk  = (const float*)d_in[4];
    const float* Wv  = (const float*)d_in[5];
    const float* bv  = (const float*)d_in[6];
    const float* W0  = (const float*)d_in[7];
    const float* b0  = (const float*)d_in[8];
    const float* g1  = (const float*)d_in[9];
    const float* be1 = (const float*)d_in[10];
    const float* W1  = (const float*)d_in[11];
    const float* b1  = (const float*)d_in[12];
    const float* W2  = (const float*)d_in[13];
    const float* b2  = (const float*)d_in[14];
    const float* g2  = (const float*)d_in[15];
    const float* be2 = (const float*)d_in[16];
    float* out = (float*)d_out;

    float *q, *k, *v, *z, *t, *o1, *hb;
    cudaGetSymbolAddress((void**)&q, g_q);
    cudaGetSymbolAddress((void**)&k, g_k);
    cudaGetSymbolAddress((void**)&v, g_v);
    cudaGetSymbolAddress((void**)&z, g_z);
    cudaGetSymbolAddress((void**)&t, g_t);
    cudaGetSymbolAddress((void**)&o1, g_o1);
    cudaGetSymbolAddress((void**)&hb, g_h);

    cudaFuncSetAttribute(attn_kernel,
                         cudaFuncAttributeMaxDynamicSharedMemorySize, ATTN_SMEM);
    cudaFuncSetAttribute(tc_gemm<0, 0>,
                         cudaFuncAttributeMaxDynamicSharedMemorySize, GSMEM);
    cudaFuncSetAttribute(tc_gemm<0, 1>,
                         cudaFuncAttributeMaxDynamicSharedMemorySize, GSMEM);
    cudaFuncSetAttribute(tc_gemm<1, 0>,
                         cudaFuncAttributeMaxDynamicSharedMemorySize, GSMEM);

    const dim3 blk(256);
    const dim3 gD(DD / 128, MM / 128);   // N=1024
    const dim3 gF(FF / 128, MM / 128);   // N=4096

    // QKV projections (tf32 mma.sync)
    tc_gemm<0, 0><<<gD, blk, GSMEM>>>(emb, Wq, bq, nullptr, q, MM, DD, DD);
    tc_gemm<0, 0><<<gD, blk, GSMEM>>>(emb, Wk, bk, nullptr, k, MM, DD, DD);
    tc_gemm<0, 0><<<gD, blk, GSMEM>>>(emb, Wv, bv, nullptr, v, MM, DD, DD);

    // attention -> z (concat-head layout)
    attn_kernel<<<dim3(SS / 64, HH, BB), blk, ATTN_SMEM>>>(q, k, v, z);

    // W0 projection + residual(emb), then LN1 -> o1
    tc_gemm<0, 1><<<gD, blk, GSMEM>>>(z, W0, b0, emb, t, MM, DD, DD);
    ln_kernel<<<MM, blk>>>(t, g1, be1, o1);

    // FFN
    tc_gemm<1, 0><<<gF, blk, GSMEM>>>(o1, W1, b1, nullptr, hb, MM, FF, DD);
    tc_gemm<0, 1><<<gD, blk, GSMEM>>>(hb, W2, b2, o1, t, MM, DD, FF);
    ln_kernel<<<MM, blk>>>(t, g2, be2, out);
}

// round 5
// speedup vs baseline: 3.7278x; 1.8266x over previous
#include <cuda_runtime.h>
#include <cuda_bf16.h>
#include <math.h>
#include <stdint.h>

// Problem constants
#define BB 2
#define SS 2048
#define DD 1024
#define HH 16
#define DH 64
#define MM (BB * SS)          // 4096 rows
#define FF (4 * DD)           // 4096 ffn hidden
#define EPS 1e-5f

// ---------------------------------------------------------------------------
// Scratch (static device memory — allocation-free)
// ---------------------------------------------------------------------------
__device__ float g_q[MM * DD];
__device__ float g_k[MM * DD];
__device__ float g_v[MM * DD];
__device__ float g_vt[MM * DD];    // V transposed per batch: [b*DD + c][s]
__device__ float g_z[MM * DD];     // attn out
__device__ float g_t[MM * DD];     // LN inputs (reused)
__device__ float g_o1[MM * DD];    // LN1 output (residual + A of FFN)
__device__ float g_h[MM * FF];     // ffn hidden

// ---------------------------------------------------------------------------
// Helpers
// ---------------------------------------------------------------------------
__device__ __forceinline__ uint32_t tf32u(float x) {
    uint32_t u = __float_as_uint(x), r;
    asm("cvt.rna.tf32.f32 %0, %1;" : "=r"(r) : "r"(u));
    return r;
}
__device__ __forceinline__ float tf32r(float x) {
    return __uint_as_float(tf32u(x));
}
__device__ __forceinline__ uint32_t su32(const void* p) {
    return (uint32_t)__cvta_generic_to_shared(p);
}
__device__ __forceinline__ void ldsm_x4(uint32_t* r, uint32_t addr) {
    asm volatile("ldmatrix.sync.aligned.m8n8.x4.shared.b16 {%0,%1,%2,%3}, [%4];"
                 : "=r"(r[0]), "=r"(r[1]), "=r"(r[2]), "=r"(r[3]) : "r"(addr));
}
__device__ __forceinline__ void mma_tf32(float* d, const uint32_t* a,
                                         const uint32_t b0, const uint32_t b1) {
    asm volatile(
        "mma.sync.aligned.m16n8k8.row.col.f32.tf32.tf32.f32 "
        "{%0,%1,%2,%3}, {%4,%5,%6,%7}, {%8,%9}, {%0,%1,%2,%3};"
        : "+f"(d[0]), "+f"(d[1]), "+f"(d[2]), "+f"(d[3])
        : "r"(a[0]), "r"(a[1]), "r"(a[2]), "r"(a[3]), "r"(b0), "r"(b1));
}
#define CPA16(dst, src) \
    asm volatile("cp.async.cg.shared.global [%0], [%1], 16;" :: "r"(dst), "l"(src))
#define CPCOMMIT() asm volatile("cp.async.commit_group;" ::: "memory")
#define CPWAIT(n)  asm volatile("cp.async.wait_group %0;" :: "n"(n) : "memory")

// SW128 swizzle on byte offsets (rows of 128B): chunk' = chunk ^ (row%8)
#define SWZ(x) ((x) ^ (((x) >> 3) & 0x70))

// ---------------------------------------------------------------------------
// tf32 mma.sync GEMM: C[M,N] = A[M,K] @ B[N,K]^T + bias (+ReLU) (+res) (+round)
// CTA tile 128x128, K-tile 32, double-buffered smem; 8 warps 2x4.
// ---------------------------------------------------------------------------
#define GSMEM 65536

template <int RELU, int RES, int ROUND>
__global__ __launch_bounds__(256) void tc_gemm(
    const float* __restrict__ A, const float* __restrict__ B,
    const float* __restrict__ bias, const float* __restrict__ res,
    float* __restrict__ C, int M, int N, int K)
{
    extern __shared__ __align__(1024) char smem[];
    const int tid = threadIdx.x;
    const int lane = tid & 31, wid = tid >> 5;
    const int bm = blockIdx.y * 128, bn = blockIdx.x * 128;

    const int wm = (wid >> 2) * 64;
    const int wn = (wid & 3) * 32;

    const int q = lane >> 3, r8 = lane & 7;
    const int ha = q >> 1;
    const int hb = q & 1;

    const uint32_t sbase = su32(smem);
    uint32_t aRow[4], bRow[2];
#pragma unroll
    for (int m = 0; m < 4; m++)
        aRow[m] = (uint32_t)((wm + m * 16 + (q & 1) * 8 + r8) * 128);
#pragma unroll
    for (int p = 0; p < 2; p++)
        bRow[p] = (uint32_t)((wn + p * 16 + (q >> 1) * 8 + r8) * 128);

    float acc[4][4][4];
#pragma unroll
    for (int m = 0; m < 4; m++)
#pragma unroll
        for (int n = 0; n < 4; n++)
#pragma unroll
            for (int e = 0; e < 4; e++) acc[m][n][e] = 0.f;

    const int nk = K / 32;

    {
        char* sA = smem;
        char* sB = smem + 16384;
#pragma unroll
        for (int i = 0; i < 4; i++) {
            int c = i * 256 + tid, row = c >> 3, cc = c & 7;
            float4 a = *(const float4*)(A + (size_t)(bm + row) * K + cc * 4);
            float4 b = *(const float4*)(B + (size_t)(bn + row) * K + cc * 4);
            int off = SWZ(row * 128 + cc * 16);
            *(uint4*)(sA + off) = make_uint4(tf32u(a.x), tf32u(a.y), tf32u(a.z), tf32u(a.w));
            *(uint4*)(sB + off) = make_uint4(tf32u(b.x), tf32u(b.y), tf32u(b.z), tf32u(b.w));
        }
    }
    __syncthreads();

    for (int kt = 0; kt < nk; kt++) {
        float4 ra[4], rb[4];
        if (kt + 1 < nk) {
#pragma unroll
            for (int i = 0; i < 4; i++) {
                int c = i * 256 + tid, row = c >> 3, cc = c & 7;
                ra[i] = *(const float4*)(A + (size_t)(bm + row) * K + (kt + 1) * 32 + cc * 4);
                rb[i] = *(const float4*)(B + (size_t)(bn + row) * K + (kt + 1) * 32 + cc * 4);
            }
        }

        const uint32_t abase = sbase + (kt & 1) * 32768u;
        const uint32_t bbase = abase + 16384u;
#pragma unroll
        for (int s = 0; s < 4; s++) {
            const uint32_t ca = (uint32_t)((((s << 1) | ha) ^ r8) << 4);
            const uint32_t cb = (uint32_t)((((s << 1) | hb) ^ r8) << 4);
            uint32_t af[4][4], bf[2][4];
#pragma unroll
            for (int m = 0; m < 4; m++) ldsm_x4(af[m], abase + aRow[m] + ca);
#pragma unroll
            for (int p = 0; p < 2; p++) ldsm_x4(bf[p], bbase + bRow[p] + cb);
#pragma unroll
            for (int m = 0; m < 4; m++) {
#pragma unroll
                for (int nt = 0; nt < 4; nt++) {
                    const int p = nt >> 1, e = (nt & 1) * 2;
                    mma_tf32(acc[m][nt], af[m], bf[p][e], bf[p][e + 1]);
                }
            }
        }

        if (kt + 1 < nk) {
            char* sA = smem + ((kt + 1) & 1) * 32768;
            char* sB = sA + 16384;
#pragma unroll
            for (int i = 0; i < 4; i++) {
                int c = i * 256 + tid, row = c >> 3, cc = c & 7;
                int off = SWZ(row * 128 + cc * 16);
                *(uint4*)(sA + off) = make_uint4(tf32u(ra[i].x), tf32u(ra[i].y),
                                                 tf32u(ra[i].z), tf32u(ra[i].w));
                *(uint4*)(sB + off) = make_uint4(tf32u(rb[i].x), tf32u(rb[i].y),
                                                 tf32u(rb[i].z), tf32u(rb[i].w));
            }
        }
        __syncthreads();
    }

    const int gid = lane >> 2, tig = lane & 3;
#pragma unroll
    for (int m = 0; m < 4; m++) {
#pragma unroll
        for (int hf = 0; hf < 2; hf++) {
            const int row = bm + wm + m * 16 + gid + hf * 8;
#pragma unroll
            for (int nt = 0; nt < 4; nt++) {
                const int col = bn + wn + nt * 8 + tig * 2;
                const size_t idx = (size_t)row * N + col;
                float2 bi = *(const float2*)(bias + col);
                float o0 = acc[m][nt][hf * 2 + 0] + bi.x;
                float o1 = acc[m][nt][hf * 2 + 1] + bi.y;
                if (RELU) { o0 = fmaxf(o0, 0.f); o1 = fmaxf(o1, 0.f); }
                if (RES) {
                    float2 rr = *(const float2*)(res + idx);
                    o0 += rr.x; o1 += rr.y;
                }
                if (ROUND) { o0 = tf32r(o0); o1 = tf32r(o1); }
                *(float2*)(C + idx) = make_float2(o0, o1);
            }
        }
    }
}

// ---------------------------------------------------------------------------
// V transpose: g_v [b*SS+s][c] -> g_vt [b*DD + c][s]
// ---------------------------------------------------------------------------
__global__ __launch_bounds__(256) void transpose_v(
    const float* __restrict__ v, float* __restrict__ vt)
{
    __shared__ float tile[32][33];
    const int tx = threadIdx.x, ty = threadIdx.y;
    const int s0 = blockIdx.x * 32, c0 = blockIdx.y * 32, b = blockIdx.z;
    const float* vb = v + (size_t)b * SS * DD;
    float* vtb = vt + (size_t)b * DD * SS;
#pragma unroll
    for (int i = 0; i < 4; i++)
        tile[ty + i * 8][tx] = vb[(size_t)(s0 + ty + i * 8) * DD + c0 + tx];
    __syncthreads();
#pragma unroll
    for (int i = 0; i < 4; i++)
        vtb[(size_t)(c0 + ty + i * 8) * SS + s0 + tx] = tile[tx][ty + i * 8];
}

// ---------------------------------------------------------------------------
// tf32 mma flash attention. Per (b,h): BQ=64 (4 warps x m16), BK=64, DH=64.
// Q frags in registers; K and V^T tiles double-buffered via cp.async.
// Online softmax in registers; P converted C-frag -> A-frag via shuffles.
// smem rows are 256B (64 floats), swizzle: chunk ^= row%8.
// ---------------------------------------------------------------------------
#define ASMEM (16384 + 2 * 16384 + 2 * 16384)   // Q + K[2] + Vt[2] = 80KB

__global__ __launch_bounds__(128) void attn_mma(
    const float* __restrict__ Q, const float* __restrict__ K,
    const float* __restrict__ Vt, float* __restrict__ O)
{
    extern __shared__ __align__(1024) char asm_[];
    const int tid = threadIdx.x, lane = tid & 31, w = tid >> 5;
    const int q2 = lane >> 3, r8 = lane & 7;
    const int gid = lane >> 2, tig = lane & 3;
    const int b = blockIdx.z, h = blockIdx.y, qb = blockIdx.x * 64;

    const uint32_t sb = su32(asm_);
    const uint32_t qs = sb;
    const uint32_t ks = sb + 16384;
    const uint32_t vs = sb + 49152;

    const float* Qg = Q + ((size_t)(b * SS + qb)) * DD + h * DH;
    const float* Kg = K + ((size_t)b * SS) * DD + h * DH;
    const float* Vg = Vt + ((size_t)(b * DD + h * DH)) * SS;

    // stage Q (group 0)
#pragma unroll
    for (int i = 0; i < 8; i++) {
        int id = i * 128 + tid, row = id >> 4, c = id & 15;
        CPA16(qs + row * 256 + ((c ^ (row & 7)) << 4),
              Qg + (size_t)row * DD + c * 4);
    }
    CPCOMMIT();
    // stage KV tile 0 (group 1)
#pragma unroll
    for (int i = 0; i < 8; i++) {
        int id = i * 128 + tid, row = id >> 4, c = id & 15;
        uint32_t soff = row * 256 + ((c ^ (row & 7)) << 4);
        CPA16(ks + soff, Kg + (size_t)row * DD + c * 4);
        CPA16(vs + soff, Vg + (size_t)row * SS + c * 4);
    }
    CPCOMMIT();

    CPWAIT(1);          // Q resident
    __syncthreads();

    // Q A-frags
    uint32_t qf[8][4];
    {
        const uint32_t aRow = (uint32_t)((w * 16 + (q2 & 1) * 8 + r8) * 256);
#pragma unroll
        for (int s = 0; s < 8; s++)
            ldsm_x4(qf[s], qs + aRow + ((((s << 1) | (q2 >> 1)) ^ r8) << 4));
    }

    float oacc[8][4];
#pragma unroll
    for (int nt = 0; nt < 8; nt++)
#pragma unroll
        for (int e = 0; e < 4; e++) oacc[nt][e] = 0.f;
    float mrow[2] = {-1e30f, -1e30f};
    float lrow[2] = {0.f, 0.f};

    const uint32_t bRowOff = (uint32_t)(((q2 >> 1) * 8 + r8) * 256);
    const uint32_t hbb = (uint32_t)(q2 & 1);
    const int src0 = (lane & ~3) | (tig >> 1);
    const int src1 = src0 | 2;
    const bool odd = (tig & 1) != 0;

    const int NT = SS / 64;   // 32 kv tiles
    for (int t = 0; t < NT; t++) {
        const uint32_t kb_ = ks + (t & 1) * 16384u;
        const uint32_t vb_ = vs + (t & 1) * 16384u;

        if (t + 1 < NT) {
            const int kb = (t + 1) * 64;
            const uint32_t kd = ks + ((t + 1) & 1) * 16384u;
            const uint32_t vd = vs + ((t + 1) & 1) * 16384u;
#pragma unroll
            for (int i = 0; i < 8; i++) {
                int id = i * 128 + tid, row = id >> 4, c = id & 15;
                uint32_t soff = row * 256 + ((c ^ (row & 7)) << 4);
                CPA16(kd + soff, Kg + (size_t)(kb + row) * DD + c * 4);
                CPA16(vd + soff, Vg + (size_t)row * SS + kb + c * 4);
            }
            CPCOMMIT();
            CPWAIT(1);
        } else {
            CPWAIT(0);
        }
        __syncthreads();

        // ---- S = Q @ K^T  (16q x 64kv per warp) ----
        float sacc[8][4];
#pragma unroll
        for (int nt = 0; nt < 8; nt++)
#pragma unroll
            for (int e = 0; e < 4; e++) sacc[nt][e] = 0.f;
#pragma unroll
        for (int s = 0; s < 8; s++) {
            uint32_t kf[4][4];
            const uint32_t cb = ((((uint32_t)s << 1) | hbb) ^ r8) << 4;
#pragma unroll
            for (int p = 0; p < 4; p++)
                ldsm_x4(kf[p], kb_ + bRowOff + p * 4096u + cb);
#pragma unroll
            for (int nt = 0; nt < 8; nt++)
                mma_tf32(sacc[nt], qf[s], kf[nt >> 1][(nt & 1) * 2],
                         kf[nt >> 1][(nt & 1) * 2 + 1]);
        }

        // ---- online softmax (rows gid, gid+8) ----
#pragma unroll
        for (int hh = 0; hh < 2; hh++) {
            float mx = -1e30f;
#pragma unroll
            for (int nt = 0; nt < 8; nt++)
                mx = fmaxf(mx, fmaxf(sacc[nt][hh * 2], sacc[nt][hh * 2 + 1]));
            mx = fmaxf(mx, __shfl_xor_sync(0xffffffffu, mx, 1));
            mx = fmaxf(mx, __shfl_xor_sync(0xffffffffu, mx, 2));
            const float mn = fmaxf(mrow[hh], mx);
            const float sc = __expf(mrow[hh] - mn);
            float sum = 0.f;
#pragma unroll
            for (int nt = 0; nt < 8; nt++) {
                float p0 = __expf(sacc[nt][hh * 2] - mn);
                float p1 = __expf(sacc[nt][hh * 2 + 1] - mn);
                sacc[nt][hh * 2] = p0;
                sacc[nt][hh * 2 + 1] = p1;
                sum += p0 + p1;
            }
            sum += __shfl_xor_sync(0xffffffffu, sum, 1);
            sum += __shfl_xor_sync(0xffffffffu, sum, 2);
            lrow[hh] = lrow[hh] * sc + sum;
            mrow[hh] = mn;
#pragma unroll
            for (int nt = 0; nt < 8; nt++) {
                oacc[nt][hh * 2] *= sc;
                oacc[nt][hh * 2 + 1] *= sc;
            }
        }

        // ---- P: C-frag -> tf32 A-frag (in place) ----
        uint32_t pf[8][4];
#pragma unroll
        for (int t8 = 0; t8 < 8; t8++) {
            uint32_t c0 = tf32u(sacc[t8][0]);
            uint32_t c1 = tf32u(sacc[t8][1]);
            uint32_t c2 = tf32u(sacc[t8][2]);
            uint32_t c3 = tf32u(sacc[t8][3]);
            uint32_t u00 = __shfl_sync(0xffffffffu, c0, src0);
            uint32_t u01 = __shfl_sync(0xffffffffu, c1, src0);
            uint32_t u10 = __shfl_sync(0xffffffffu, c2, src0);
            uint32_t u11 = __shfl_sync(0xffffffffu, c3, src0);
            uint32_t u20 = __shfl_sync(0xffffffffu, c0, src1);
            uint32_t u21 = __shfl_sync(0xffffffffu, c1, src1);
            uint32_t u30 = __shfl_sync(0xffffffffu, c2, src1);
            uint32_t u31 = __shfl_sync(0xffffffffu, c3, src1);
            pf[t8][0] = odd ? u01 : u00;
            pf[t8][1] = odd ? u11 : u10;
            pf[t8][2] = odd ? u21 : u20;
            pf[t8][3] = odd ? u31 : u30;
        }

        // ---- O += P @ V  (k = kv, n = dh) ----
#pragma unroll
        for (int t8 = 0; t8 < 8; t8++) {
            uint32_t vf[4][4];
            const uint32_t cb = ((((uint32_t)t8 << 1) | hbb) ^ r8) << 4;
#pragma unroll
            for (int p = 0; p < 4; p++)
                ldsm_x4(vf[p], vb_ + bRowOff + p * 4096u + cb);
#pragma unroll
            for (int nt = 0; nt < 8; nt++)
                mma_tf32(oacc[nt], pf[t8], vf[nt >> 1][(nt & 1) * 2],
                         vf[nt >> 1][(nt & 1) * 2 + 1]);
        }
        __syncthreads();
    }

    // ---- write O (concat-head layout), scaled by 1/(l*sqrt(64)) ----
    float* Og = O + ((size_t)(b * SS + qb)) * DD + h * DH;
#pragma unroll
    for (int hh = 0; hh < 2; hh++) {
        const float invl = 0.125f / lrow[hh];
        const int row = w * 16 + gid + hh * 8;
#pragma unroll
        for (int nt = 0; nt < 8; nt++) {
            const int col = nt * 8 + tig * 2;
            *(float2*)(Og + (size_t)row * DD + col) =
                make_float2(oacc[nt][hh * 2] * invl, oacc[nt][hh * 2 + 1] * invl);
        }
    }
}

// ---------------------------------------------------------------------------
// LayerNorm over D=1024
// ---------------------------------------------------------------------------
__global__ __launch_bounds__(256) void ln_kernel(
    const float* __restrict__ x, const float* __restrict__ g,
    const float* __restrict__ be, float* __restrict__ out)
{
    const int row = blockIdx.x;
    const int tid = threadIdx.x;
    const float* xr = x + (size_t)row * DD;

    float4 xv = *(const float4*)(xr + tid * 4);
    float sum = xv.x + xv.y + xv.z + xv.w;
    float sq = xv.x * xv.x + xv.y * xv.y + xv.z * xv.z + xv.w * xv.w;

    __shared__ float s1[32], s2[32];
#pragma unroll
    for (int o = 16; o > 0; o >>= 1) {
        sum += __shfl_xor_sync(0xffffffffu, sum, o);
        sq += __shfl_xor_sync(0xffffffffu, sq, o);
    }
    const int w = tid >> 5, l = tid & 31;
    if (l == 0) { s1[w] = sum; s2[w] = sq; }
    __syncthreads();
    if (w == 0) {
        sum = (l < 8) ? s1[l] : 0.f;
        sq = (l < 8) ? s2[l] : 0.f;
#pragma unroll
        for (int o = 4; o > 0; o >>= 1) {
            sum += __shfl_xor_sync(0xffffffffu, sum, o);
            sq += __shfl_xor_sync(0xffffffffu, sq, o);
        }
        if (l == 0) { s1[0] = sum; s2[0] = sq; }
    }
    __syncthreads();
    const float mu = s1[0] * (1.f / DD);
    const float var = s2[0] * (1.f / DD) - mu * mu;
    const float rstd = rsqrtf(var + EPS);

    float4 gv = *(const float4*)(g + tid * 4);
    float4 bv = *(const float4*)(be + tid * 4);
    float4 ov;
    ov.x = (xv.x - mu) * rstd * gv.x + bv.x;
    ov.y = (xv.y - mu) * rstd * gv.y + bv.y;
    ov.z = (xv.z - mu) * rstd * gv.z + bv.z;
    ov.w = (xv.w - mu) * rstd * gv.w + bv.w;
    *(float4*)(out + (size_t)row * DD + tid * 4) = ov;
}

// ---------------------------------------------------------------------------
// Launch
// ---------------------------------------------------------------------------
extern "C" void kernel_launch(void* const* d_in, const int* in_sizes, int n_in,
                              void* d_out, int out_size)
{
    const float* emb = (const float*)d_in[0];
    const float* Wq  = (const float*)d_in[1];
    const float* bq  = (const float*)d_in[2];
    const float* Wk  = (const float*)d_in[3];
    const float* bk  = (const float*)d_in[4];
    const float* Wv  = (const float*)d_in[5];
    const float* bv  = (const float*)d_in[6];
    const float* W0  = (const float*)d_in[7];
    const float* b0  = (const float*)d_in[8];
    const float* g1  = (const float*)d_in[9];
    const float* be1 = (const float*)d_in[10];
    const float* W1  = (const float*)d_in[11];
    const float* b1  = (const float*)d_in[12];
    const float* W2  = (const float*)d_in[13];
    const float* b2  = (const float*)d_in[14];
    const float* g2  = (const float*)d_in[15];
    const float* be2 = (const float*)d_in[16];
    float* out = (float*)d_out;

    float *q, *k, *v, *vt, *z, *t, *o1, *hb;
    cudaGetSymbolAddress((void**)&q, g_q);
    cudaGetSymbolAddress((void**)&k, g_k);
    cudaGetSymbolAddress((void**)&v, g_v);
    cudaGetSymbolAddress((void**)&vt, g_vt);
    cudaGetSymbolAddress((void**)&z, g_z);
    cudaGetSymbolAddress((void**)&t, g_t);
    cudaGetSymbolAddress((void**)&o1, g_o1);
    cudaGetSymbolAddress((void**)&hb, g_h);

    cudaFuncSetAttribute(attn_mma,
                         cudaFuncAttributeMaxDynamicSharedMemorySize, ASMEM);
    cudaFuncSetAttribute(tc_gemm<0, 0, 1>,
                         cudaFuncAttributeMaxDynamicSharedMemorySize, GSMEM);
    cudaFuncSetAttribute(tc_gemm<0, 1, 0>,
                         cudaFuncAttributeMaxDynamicSharedMemorySize, GSMEM);
    cudaFuncSetAttribute(tc_gemm<1, 0, 0>,
                         cudaFuncAttributeMaxDynamicSharedMemorySize, GSMEM);

    const dim3 blk(256);
    const dim3 gD(DD / 128, MM / 128);   // N=1024
    const dim3 gF(FF / 128, MM / 128);   // N=4096

    // QKV projections (tf32 mma.sync), outputs rounded to tf32
    tc_gemm<0, 0, 1><<<gD, blk, GSMEM>>>(emb, Wq, bq, nullptr, q, MM, DD, DD);
    tc_gemm<0, 0, 1><<<gD, blk, GSMEM>>>(emb, Wk, bk, nullptr, k, MM, DD, DD);
    tc_gemm<0, 0, 1><<<gD, blk, GSMEM>>>(emb, Wv, bv, nullptr, v, MM, DD, DD);

    // V transpose for the PV mma
    transpose_v<<<dim3(SS / 32, DD / 32, BB), dim3(32, 8)>>>(v, vt);

    // attention -> z (concat-head layout)
    attn_mma<<<dim3(SS / 64, HH, BB), dim3(128), ASMEM>>>(q, k, vt, z);

    // W0 projection + residual(emb), then LN1 -> o1
    tc_gemm<0, 1, 0><<<gD, blk, GSMEM>>>(z, W0, b0, emb, t, MM, DD, DD);
    ln_kernel<<<MM, blk>>>(t, g1, be1, o1);

    // FFN
    tc_gemm<1, 0, 0><<<gF, blk, GSMEM>>>(o1, W1, b1, nullptr, hb, MM, FF, DD);
    tc_gemm<0, 1, 0><<<gD, blk, GSMEM>>>(hb, W2, b2, o1, t, MM, DD, FF);
    ln_kernel<<<MM, blk>>>(t, g2, be2, out);
}

// round 7
// speedup vs baseline: 4.0904x; 1.0973x over previous
#include <cuda_runtime.h>
#include <cuda_bf16.h>
#include <math.h>
#include <stdint.h>

// Problem constants
#define BB 2
#define SS 2048
#define DD 1024
#define HH 16
#define DH 64
#define MM (BB * SS)          // 4096 rows
#define FF (4 * DD)           // 4096 ffn hidden
#define EPS 1e-5f

// ---------------------------------------------------------------------------
// Scratch (static device memory — allocation-free)
// ---------------------------------------------------------------------------
__device__ float g_q[MM * DD];
__device__ float g_k[MM * DD];
__device__ float g_v[MM * DD];
__device__ float g_vt[MM * DD];    // V transposed per batch: [b*DD + c][s]
__device__ float g_z[MM * DD];     // attn out (tf32-rounded at write)
__device__ float g_t[MM * DD];     // LN inputs (reused)
__device__ float g_o1[MM * DD];    // LN1 output exact (residual)
__device__ float g_o1r[MM * DD];   // LN1 output tf32-rounded (GEMM A)
__device__ float g_h[MM * FF];     // ffn hidden (tf32-rounded in epilogue)
// pre-rounded operands
__device__ float g_embr[MM * DD];
__device__ float g_wqr[DD * DD];
__device__ float g_wkr[DD * DD];
__device__ float g_wvr[DD * DD];
__device__ float g_w0r[DD * DD];
__device__ float g_w1r[FF * DD];
__device__ float g_w2r[FF * DD];

// ---------------------------------------------------------------------------
// Helpers
// ---------------------------------------------------------------------------
__device__ __forceinline__ uint32_t tf32u(float x) {
    uint32_t u = __float_as_uint(x), r;
    asm("cvt.rna.tf32.f32 %0, %1;" : "=r"(r) : "r"(u));
    return r;
}
__device__ __forceinline__ float tf32r(float x) {
    return __uint_as_float(tf32u(x));
}
__device__ __forceinline__ uint32_t su32(const void* p) {
    return (uint32_t)__cvta_generic_to_shared(p);
}
__device__ __forceinline__ void ldsm_x4(uint32_t* r, uint32_t addr) {
    asm volatile("ldmatrix.sync.aligned.m8n8.x4.shared.b16 {%0,%1,%2,%3}, [%4];"
                 : "=r"(r[0]), "=r"(r[1]), "=r"(r[2]), "=r"(r[3]) : "r"(addr));
}
__device__ __forceinline__ void mma_tf32(float* d, const uint32_t* a,
                                         const uint32_t b0, const uint32_t b1) {
    asm volatile(
        "mma.sync.aligned.m16n8k8.row.col.f32.tf32.tf32.f32 "
        "{%0,%1,%2,%3}, {%4,%5,%6,%7}, {%8,%9}, {%0,%1,%2,%3};"
        : "+f"(d[0]), "+f"(d[1]), "+f"(d[2]), "+f"(d[3])
        : "r"(a[0]), "r"(a[1]), "r"(a[2]), "r"(a[3]), "r"(b0), "r"(b1));
}
#define CPA16(dst, src) \
    asm volatile("cp.async.cg.shared.global [%0], [%1], 16;" :: "r"(dst), "l"(src))
#define CPCOMMIT() asm volatile("cp.async.commit_group;" ::: "memory")
#define CPWAIT(n)  asm volatile("cp.async.wait_group %0;" :: "n"(n) : "memory")

// SW128 swizzle on byte offsets (rows of 128B): chunk' = chunk ^ (row%8)
#define SWZ(x) ((x) ^ (((x) >> 3) & 0x70))

// ---------------------------------------------------------------------------
// GEMM compute core shared pieces (macros to keep one code path)
// Stage = A tile 16KB + B tile 16KB = 32KB. 4 stages = 128KB.
// ---------------------------------------------------------------------------
#define GSMEM (4 * 32768)

#define GEMM_ISSUE_STAGE(st, kt, Ap, Bp)                                        \
    do {                                                                        \
        const uint32_t _sA = sbase + (uint32_t)(st) * 32768u;                   \
        const uint32_t _sB = _sA + 16384u;                                      \
        _Pragma("unroll")                                                       \
        for (int _i = 0; _i < 4; _i++) {                                        \
            int _id = _i * 256 + tid, _row = _id >> 3, _cc = _id & 7;           \
            uint32_t _off = (uint32_t)SWZ(_row * 128 + _cc * 16);               \
            CPA16(_sA + _off, (Ap) + (size_t)(bm + _row) * K + (kt) * 32 + _cc * 4); \
            CPA16(_sB + _off, (Bp) + (size_t)(bn + _row) * K + (kt) * 32 + _cc * 4); \
        }                                                                       \
    } while (0)

#define GEMM_COMPUTE_STAGE(st)                                                  \
    do {                                                                        \
        const uint32_t abase = sbase + (uint32_t)(st) * 32768u;                 \
        const uint32_t bbase = abase + 16384u;                                  \
        _Pragma("unroll")                                                       \
        for (int s = 0; s < 4; s++) {                                           \
            const uint32_t ca = (uint32_t)((((s << 1) | ha) ^ r8) << 4);        \
            const uint32_t cb = (uint32_t)((((s << 1) | hb) ^ r8) << 4);        \
            uint32_t af[4][4], bf[2][4];                                        \
            _Pragma("unroll")                                                   \
            for (int m = 0; m < 4; m++) ldsm_x4(af[m], abase + aRow[m] + ca);   \
            _Pragma("unroll")                                                   \
            for (int p = 0; p < 2; p++) ldsm_x4(bf[p], bbase + bRow[p] + cb);   \
            _Pragma("unroll")                                                   \
            for (int m = 0; m < 4; m++) {                                       \
                _Pragma("unroll")                                               \
                for (int nt = 0; nt < 4; nt++) {                                \
                    const int p = nt >> 1, e = (nt & 1) * 2;                    \
                    mma_tf32(acc[m][nt], af[m], bf[p][e], bf[p][e + 1]);        \
                }                                                               \
            }                                                                   \
        }                                                                       \
    } while (0)

#define GEMM_PREAMBLE()                                                         \
    const int tid = threadIdx.x;                                                \
    const int lane = tid & 31, wid = tid >> 5;                                  \
    const int wm = (wid >> 2) * 64;                                             \
    const int wn = (wid & 3) * 32;                                              \
    const int q = lane >> 3, r8 = lane & 7;                                     \
    const int ha = q >> 1;                                                      \
    const int hb = q & 1;                                                       \
    const uint32_t sbase = su32(smem);                                          \
    uint32_t aRow[4], bRow[2];                                                  \
    _Pragma("unroll")                                                           \
    for (int m = 0; m < 4; m++)                                                 \
        aRow[m] = (uint32_t)((wm + m * 16 + (q & 1) * 8 + r8) * 128);           \
    _Pragma("unroll")                                                           \
    for (int p = 0; p < 2; p++)                                                 \
        bRow[p] = (uint32_t)((wn + p * 16 + (q >> 1) * 8 + r8) * 128);          \
    float acc[4][4][4];                                                         \
    _Pragma("unroll")                                                           \
    for (int m = 0; m < 4; m++)                                                 \
        _Pragma("unroll")                                                       \
        for (int n = 0; n < 4; n++)                                             \
            _Pragma("unroll")                                                   \
            for (int e = 0; e < 4; e++) acc[m][n][e] = 0.f;

#define GEMM_MAINLOOP(Ap, Bp)                                                   \
    const int nk = K / 32;                                                      \
    for (int s = 0; s < 3; s++) {                                               \
        if (s < nk) GEMM_ISSUE_STAGE(s, s, Ap, Bp);                             \
        CPCOMMIT();                                                             \
    }                                                                           \
    for (int kt = 0; kt < nk; kt++) {                                           \
        CPWAIT(2);                                                              \
        __syncthreads();                                                        \
        if (kt + 3 < nk) GEMM_ISSUE_STAGE((kt + 3) & 3, kt + 3, Ap, Bp);        \
        CPCOMMIT();                                                             \
        GEMM_COMPUTE_STAGE(kt & 3);                                             \
    }

#define GEMM_EPILOGUE(Cp, biasp, resp, RELU, RES, ROUND)                        \
    do {                                                                        \
        const int gid = lane >> 2, tig = lane & 3;                              \
        _Pragma("unroll")                                                       \
        for (int m = 0; m < 4; m++) {                                           \
            _Pragma("unroll")                                                   \
            for (int hf = 0; hf < 2; hf++) {                                    \
                const int row = bm + wm + m * 16 + gid + hf * 8;                \
                _Pragma("unroll")                                               \
                for (int nt = 0; nt < 4; nt++) {                                \
                    const int col = bn + wn + nt * 8 + tig * 2;                 \
                    const size_t idx = (size_t)row * N + col;                   \
                    float2 bi = *(const float2*)((biasp) + col);                \
                    float o0 = acc[m][nt][hf * 2 + 0] + bi.x;                   \
                    float o1 = acc[m][nt][hf * 2 + 1] + bi.y;                   \
                    if (RELU) { o0 = fmaxf(o0, 0.f); o1 = fmaxf(o1, 0.f); }     \
                    if (RES) {                                                  \
                        float2 rr = *(const float2*)((resp) + idx);             \
                        o0 += rr.x; o1 += rr.y;                                 \
                    }                                                           \
                    if (ROUND) { o0 = tf32r(o0); o1 = tf32r(o1); }              \
                    *(float2*)((Cp) + idx) = make_float2(o0, o1);               \
                }                                                               \
            }                                                                   \
        }                                                                       \
    } while (0)

// ---------------------------------------------------------------------------
// Generic GEMM: C[M,N] = A[M,K] @ B[N,K]^T + bias (+ReLU/res/round).
// A, B must be pre-rounded tf32 values in gmem.
// ---------------------------------------------------------------------------
template <int RELU, int RES, int ROUND>
__global__ __launch_bounds__(256) void tc_gemm(
    const float* __restrict__ A, const float* __restrict__ B,
    const float* __restrict__ bias, const float* __restrict__ res,
    float* __restrict__ C, int M, int N, int K)
{
    extern __shared__ __align__(1024) char smem[];
    const int bm = blockIdx.y * 128, bn = blockIdx.x * 128;
    GEMM_PREAMBLE();
    GEMM_MAINLOOP(A, B);
    GEMM_EPILOGUE(C, bias, res, RELU, RES, ROUND);
}

// ---------------------------------------------------------------------------
// Merged QKV GEMM: one launch covers q/k/v (select by blockIdx.x>>3).
// Outputs tf32-rounded.
// ---------------------------------------------------------------------------
__global__ __launch_bounds__(256) void tc_gemm_qkv(
    const float* __restrict__ A,
    const float* __restrict__ Wq, const float* __restrict__ Wk,
    const float* __restrict__ Wv,
    const float* __restrict__ bq, const float* __restrict__ bk,
    const float* __restrict__ bv,
    float* __restrict__ Cq, float* __restrict__ Ck, float* __restrict__ Cv)
{
    extern __shared__ __align__(1024) char smem[];
    const int N = DD, K = DD;
    const int sel = blockIdx.x >> 3;
    const int bm = blockIdx.y * 128, bn = (blockIdx.x & 7) * 128;
    const float* B = (sel == 0) ? Wq : (sel == 1) ? Wk : Wv;
    const float* bias = (sel == 0) ? bq : (sel == 1) ? bk : bv;
    float* C = (sel == 0) ? Cq : (sel == 1) ? Ck : Cv;
    GEMM_PREAMBLE();
    GEMM_MAINLOOP(A, B);
    GEMM_EPILOGUE(C, bias, (const float*)nullptr, 0, 0, 1);
}

// ---------------------------------------------------------------------------
// tf32 rounding pass
// ---------------------------------------------------------------------------
__global__ __launch_bounds__(256) void round_kernel(
    const float4* __restrict__ src, float4* __restrict__ dst, int n4)
{
    int i = blockIdx.x * blockDim.x + threadIdx.x;
    if (i < n4) {
        float4 v = src[i];
        v.x = tf32r(v.x); v.y = tf32r(v.y); v.z = tf32r(v.z); v.w = tf32r(v.w);
        dst[i] = v;
    }
}

// ---------------------------------------------------------------------------
// V transpose: g_v [b*SS+s][c] -> g_vt [b*DD + c][s]
// ---------------------------------------------------------------------------
__global__ __launch_bounds__(256) void transpose_v(
    const float* __restrict__ v, float* __restrict__ vt)
{
    __shared__ float tile[32][33];
    const int tx = threadIdx.x, ty = threadIdx.y;
    const int s0 = blockIdx.x * 32, c0 = blockIdx.y * 32, b = blockIdx.z;
    const float* vb = v + (size_t)b * SS * DD;
    float* vtb = vt + (size_t)b * DD * SS;
#pragma unroll
    for (int i = 0; i < 4; i++)
        tile[ty + i * 8][tx] = vb[(size_t)(s0 + ty + i * 8) * DD + c0 + tx];
    __syncthreads();
#pragma unroll
    for (int i = 0; i < 4; i++)
        vtb[(size_t)(c0 + ty + i * 8) * SS + s0 + tx] = tile[tx][ty + i * 8];
}

// ---------------------------------------------------------------------------
// tf32 mma flash attention (as R5, output tf32-rounded)
// ---------------------------------------------------------------------------
#define ASMEM (16384 + 2 * 16384 + 2 * 16384)   // Q + K[2] + Vt[2] = 80KB

__global__ __launch_bounds__(128) void attn_mma(
    const float* __restrict__ Q, const float* __restrict__ K,
    const float* __restrict__ Vt, float* __restrict__ O)
{
    extern __shared__ __align__(1024) char asm_[];
    const int tid = threadIdx.x, lane = tid & 31, w = tid >> 5;
    const int q2 = lane >> 3, r8 = lane & 7;
    const int gid = lane >> 2, tig = lane & 3;
    const int b = blockIdx.z, h = blockIdx.y, qb = blockIdx.x * 64;

    const uint32_t sb = su32(asm_);
    const uint32_t qs = sb;
    const uint32_t ks = sb + 16384;
    const uint32_t vs = sb + 49152;

    const float* Qg = Q + ((size_t)(b * SS + qb)) * DD + h * DH;
    const float* Kg = K + ((size_t)b * SS) * DD + h * DH;
    const float* Vg = Vt + ((size_t)(b * DD + h * DH)) * SS;

#pragma unroll
    for (int i = 0; i < 8; i++) {
        int id = i * 128 + tid, row = id >> 4, c = id & 15;
        CPA16(qs + row * 256 + ((c ^ (row & 7)) << 4),
              Qg + (size_t)row * DD + c * 4);
    }
    CPCOMMIT();
#pragma unroll
    for (int i = 0; i < 8; i++) {
        int id = i * 128 + tid, row = id >> 4, c = id & 15;
        uint32_t soff = row * 256 + ((c ^ (row & 7)) << 4);
        CPA16(ks + soff, Kg + (size_t)row * DD + c * 4);
        CPA16(vs + soff, Vg + (size_t)row * SS + c * 4);
    }
    CPCOMMIT();

    CPWAIT(1);
    __syncthreads();

    uint32_t qf[8][4];
    {
        const uint32_t aRow = (uint32_t)((w * 16 + (q2 & 1) * 8 + r8) * 256);
#pragma unroll
        for (int s = 0; s < 8; s++)
            ldsm_x4(qf[s], qs + aRow + ((((s << 1) | (q2 >> 1)) ^ r8) << 4));
    }

    float oacc[8][4];
#pragma unroll
    for (int nt = 0; nt < 8; nt++)
#pragma unroll
        for (int e = 0; e < 4; e++) oacc[nt][e] = 0.f;
    float mrow[2] = {-1e30f, -1e30f};
    float lrow[2] = {0.f, 0.f};

    const uint32_t bRowOff = (uint32_t)(((q2 >> 1) * 8 + r8) * 256);
    const uint32_t hbb = (uint32_t)(q2 & 1);
    const int src0 = (lane & ~3) | (tig >> 1);
    const int src1 = src0 | 2;
    const bool odd = (tig & 1) != 0;

    const int NT = SS / 64;
    for (int t = 0; t < NT; t++) {
        const uint32_t kb_ = ks + (t & 1) * 16384u;
        const uint32_t vb_ = vs + (t & 1) * 16384u;

        if (t + 1 < NT) {
            const int kb = (t + 1) * 64;
            const uint32_t kd = ks + ((t + 1) & 1) * 16384u;
            const uint32_t vd = vs + ((t + 1) & 1) * 16384u;
#pragma unroll
            for (int i = 0; i < 8; i++) {
                int id = i * 128 + tid, row = id >> 4, c = id & 15;
                uint32_t soff = row * 256 + ((c ^ (row & 7)) << 4);
                CPA16(kd + soff, Kg + (size_t)(kb + row) * DD + c * 4);
                CPA16(vd + soff, Vg + (size_t)row * SS + kb + c * 4);
            }
            CPCOMMIT();
            CPWAIT(1);
        } else {
            CPWAIT(0);
        }
        __syncthreads();

        float sacc[8][4];
#pragma unroll
        for (int nt = 0; nt < 8; nt++)
#pragma unroll
            for (int e = 0; e < 4; e++) sacc[nt][e] = 0.f;
#pragma unroll
        for (int s = 0; s < 8; s++) {
            uint32_t kf[4][4];
            const uint32_t cb = ((((uint32_t)s << 1) | hbb) ^ r8) << 4;
#pragma unroll
            for (int p = 0; p < 4; p++)
                ldsm_x4(kf[p], kb_ + bRowOff + p * 4096u + cb);
#pragma unroll
            for (int nt = 0; nt < 8; nt++)
                mma_tf32(sacc[nt], qf[s], kf[nt >> 1][(nt & 1) * 2],
                         kf[nt >> 1][(nt & 1) * 2 + 1]);
        }

#pragma unroll
        for (int hh = 0; hh < 2; hh++) {
            float mx = -1e30f;
#pragma unroll
            for (int nt = 0; nt < 8; nt++)
                mx = fmaxf(mx, fmaxf(sacc[nt][hh * 2], sacc[nt][hh * 2 + 1]));
            mx = fmaxf(mx, __shfl_xor_sync(0xffffffffu, mx, 1));
            mx = fmaxf(mx, __shfl_xor_sync(0xffffffffu, mx, 2));
            const float mn = fmaxf(mrow[hh], mx);
            const float sc = __expf(mrow[hh] - mn);
            float sum = 0.f;
#pragma unroll
            for (int nt = 0; nt < 8; nt++) {
                float p0 = __expf(sacc[nt][hh * 2] - mn);
                float p1 = __expf(sacc[nt][hh * 2 + 1] - mn);
                sacc[nt][hh * 2] = p0;
                sacc[nt][hh * 2 + 1] = p1;
                sum += p0 + p1;
            }
            sum += __shfl_xor_sync(0xffffffffu, sum, 1);
            sum += __shfl_xor_sync(0xffffffffu, sum, 2);
            lrow[hh] = lrow[hh] * sc + sum;
            mrow[hh] = mn;
#pragma unroll
            for (int nt = 0; nt < 8; nt++) {
                oacc[nt][hh * 2] *= sc;
                oacc[nt][hh * 2 + 1] *= sc;
            }
        }

        uint32_t pf[8][4];
#pragma unroll
        for (int t8 = 0; t8 < 8; t8++) {
            uint32_t c0 = tf32u(sacc[t8][0]);
            uint32_t c1 = tf32u(sacc[t8][1]);
            uint32_t c2 = tf32u(sacc[t8][2]);
            uint32_t c3 = tf32u(sacc[t8][3]);
            uint32_t u00 = __shfl_sync(0xffffffffu, c0, src0);
            uint32_t u01 = __shfl_sync(0xffffffffu, c1, src0);
            uint32_t u10 = __shfl_sync(0xffffffffu, c2, src0);
            uint32_t u11 = __shfl_sync(0xffffffffu, c3, src0);
            uint32_t u20 = __shfl_sync(0xffffffffu, c0, src1);
            uint32_t u21 = __shfl_sync(0xffffffffu, c1, src1);
            uint32_t u30 = __shfl_sync(0xffffffffu, c2, src1);
            uint32_t u31 = __shfl_sync(0xffffffffu, c3, src1);
            pf[t8][0] = odd ? u01 : u00;
            pf[t8][1] = odd ? u11 : u10;
            pf[t8][2] = odd ? u21 : u20;
            pf[t8][3] = odd ? u31 : u30;
        }

#pragma unroll
        for (int t8 = 0; t8 < 8; t8++) {
            uint32_t vf[4][4];
            const uint32_t cb = ((((uint32_t)t8 << 1) | hbb) ^ r8) << 4;
#pragma unroll
            for (int p = 0; p < 4; p++)
                ldsm_x4(vf[p], vb_ + bRowOff + p * 4096u + cb);
#pragma unroll
            for (int nt = 0; nt < 8; nt++)
                mma_tf32(oacc[nt], pf[t8], vf[nt >> 1][(nt & 1) * 2],
                         vf[nt >> 1][(nt & 1) * 2 + 1]);
        }
        __syncthreads();
    }

    float* Og = O + ((size_t)(b * SS + qb)) * DD + h * DH;
#pragma unroll
    for (int hh = 0; hh < 2; hh++) {
        const float invl = 0.125f / lrow[hh];
        const int row = w * 16 + gid + hh * 8;
#pragma unroll
        for (int nt = 0; nt < 8; nt++) {
            const int col = nt * 8 + tig * 2;
            *(float2*)(Og + (size_t)row * DD + col) =
                make_float2(tf32r(oacc[nt][hh * 2] * invl),
                            tf32r(oacc[nt][hh * 2 + 1] * invl));
        }
    }
}

// ---------------------------------------------------------------------------
// LayerNorm over D=1024; optional tf32-rounded second copy
// ---------------------------------------------------------------------------
__global__ __launch_bounds__(256) void ln_kernel(
    const float* __restrict__ x, const float* __restrict__ g,
    const float* __restrict__ be, float* __restrict__ out,
    float* __restrict__ out_r)
{
    const int row = blockIdx.x;
    const int tid = threadIdx.x;
    const float* xr = x + (size_t)row * DD;

    float4 xv = *(const float4*)(xr + tid * 4);
    float sum = xv.x + xv.y + xv.z + xv.w;
    float sq = xv.x * xv.x + xv.y * xv.y + xv.z * xv.z + xv.w * xv.w;

    __shared__ float s1[32], s2[32];
#pragma unroll
    for (int o = 16; o > 0; o >>= 1) {
        sum += __shfl_xor_sync(0xffffffffu, sum, o);
        sq += __shfl_xor_sync(0xffffffffu, sq, o);
    }
    const int w = tid >> 5, l = tid & 31;
    if (l == 0) { s1[w] = sum; s2[w] = sq; }
    __syncthreads();
    if (w == 0) {
        sum = (l < 8) ? s1[l] : 0.f;
        sq = (l < 8) ? s2[l] : 0.f;
#pragma unroll
        for (int o = 4; o > 0; o >>= 1) {
            sum += __shfl_xor_sync(0xffffffffu, sum, o);
            sq += __shfl_xor_sync(0xffffffffu, sq, o);
        }
        if (l == 0) { s1[0] = sum; s2[0] = sq; }
    }
    __syncthreads();
    const float mu = s1[0] * (1.f / DD);
    const float var = s2[0] * (1.f / DD) - mu * mu;
    const float rstd = rsqrtf(var + EPS);

    float4 gv = *(const float4*)(g + tid * 4);
    float4 bv = *(const float4*)(be + tid * 4);
    float4 ov;
    ov.x = (xv.x - mu) * rstd * gv.x + bv.x;
    ov.y = (xv.y - mu) * rstd * gv.y + bv.y;
    ov.z = (xv.z - mu) * rstd * gv.z + bv.z;
    ov.w = (xv.w - mu) * rstd * gv.w + bv.w;
    *(float4*)(out + (size_t)row * DD + tid * 4) = ov;
    if (out_r) {
        float4 rv;
        rv.x = tf32r(ov.x); rv.y = tf32r(ov.y);
        rv.z = tf32r(ov.z); rv.w = tf32r(ov.w);
        *(float4*)(out_r + (size_t)row * DD + tid * 4) = rv;
    }
}

// ---------------------------------------------------------------------------
// Launch
// ---------------------------------------------------------------------------
extern "C" void kernel_launch(void* const* d_in, const int* in_sizes, int n_in,
                              void* d_out, int out_size)
{
    const float* emb = (const float*)d_in[0];
    const float* Wq  = (const float*)d_in[1];
    const float* bq  = (const float*)d_in[2];
    const float* Wk  = (const float*)d_in[3];
    const float* bk  = (const float*)d_in[4];
    const float* Wv  = (const float*)d_in[5];
    const float* bv  = (const float*)d_in[6];
    const float* W0  = (const float*)d_in[7];
    const float* b0  = (const float*)d_in[8];
    const float* g1  = (const float*)d_in[9];
    const float* be1 = (const float*)d_in[10];
    const float* W1  = (const float*)d_in[11];
    const float* b1  = (const float*)d_in[12];
    const float* W2  = (const float*)d_in[13];
    const float* b2  = (const float*)d_in[14];
    const float* g2  = (const float*)d_in[15];
    const float* be2 = (const float*)d_in[16];
    float* out = (float*)d_out;

    float *q, *k, *v, *vt, *z, *t, *o1, *o1r, *hb;
    float *embr, *wqr, *wkr, *wvr, *w0r, *w1r, *w2r;
    cudaGetSymbolAddress((void**)&q, g_q);
    cudaGetSymbolAddress((void**)&k, g_k);
    cudaGetSymbolAddress((void**)&v, g_v);
    cudaGetSymbolAddress((void**)&vt, g_vt);
    cudaGetSymbolAddress((void**)&z, g_z);
    cudaGetSymbolAddress((void**)&t, g_t);
    cudaGetSymbolAddress((void**)&o1, g_o1);
    cudaGetSymbolAddress((void**)&o1r, g_o1r);
    cudaGetSymbolAddress((void**)&hb, g_h);
    cudaGetSymbolAddress((void**)&embr, g_embr);
    cudaGetSymbolAddress((void**)&wqr, g_wqr);
    cudaGetSymbolAddress((void**)&wkr, g_wkr);
    cudaGetSymbolAddress((void**)&wvr, g_wvr);
    cudaGetSymbolAddress((void**)&w0r, g_w0r);
    cudaGetSymbolAddress((void**)&w1r, g_w1r);
    cudaGetSymbolAddress((void**)&w2r, g_w2r);

    cudaFuncSetAttribute(attn_mma,
                         cudaFuncAttributeMaxDynamicSharedMemorySize, ASMEM);
    cudaFuncSetAttribute(tc_gemm_qkv,
                         cudaFuncAttributeMaxDynamicSharedMemorySize, GSMEM);
    cudaFuncSetAttribute(tc_gemm<0, 1, 0>,
                         cudaFuncAttributeMaxDynamicSharedMemorySize, GSMEM);
    cudaFuncSetAttribute(tc_gemm<1, 0, 1>,
                         cudaFuncAttributeMaxDynamicSharedMemorySize, GSMEM);

    const dim3 blk(256);
    const int nD = DD * DD / 4, nF = FF * DD / 4, nE = MM * DD / 4;

    // pre-round all GEMM operands to tf32 (enables raw cp.async staging)
    round_kernel<<<(nE + 255) / 256, blk>>>((const float4*)emb, (float4*)embr, nE);
    round_kernel<<<(nD + 255) / 256, blk>>>((const float4*)Wq, (float4*)wqr, nD);
    round_kernel<<<(nD + 255) / 256, blk>>>((const float4*)Wk, (float4*)wkr, nD);
    round_kernel<<<(nD + 255) / 256, blk>>>((const float4*)Wv, (float4*)wvr, nD);
    round_kernel<<<(nD + 255) / 256, blk>>>((const float4*)W0, (float4*)w0r, nD);
    round_kernel<<<(nF + 255) / 256, blk>>>((const float4*)W1, (float4*)w1r, nF);
    round_kernel<<<(nF + 255) / 256, blk>>>((const float4*)W2, (float4*)w2r, nF);

    // QKV projections — one merged launch, outputs rounded
    tc_gemm_qkv<<<dim3(24, MM / 128), blk, GSMEM>>>(
        embr, wqr, wkr, wvr, bq, bk, bv, q, k, v);

    // V transpose for the PV mma
    transpose_v<<<dim3(SS / 32, DD / 32, BB), dim3(32, 8)>>>(v, vt);

    // attention -> z (concat-head layout, rounded)
    attn_mma<<<dim3(SS / 64, HH, BB), dim3(128), ASMEM>>>(q, k, vt, z);

    // W0 projection + residual(emb), then LN1 -> o1 (exact) / o1r (rounded)
    tc_gemm<0, 1, 0><<<dim3(8, 32), blk, GSMEM>>>(z, w0r, b0, emb, t, MM, DD, DD);
    ln_kernel<<<MM, blk>>>(t, g1, be1, o1, o1r);

    // FFN
    tc_gemm<1, 0, 1><<<dim3(32, 32), blk, GSMEM>>>(o1r, w1r, b1, nullptr, hb, MM, FF, DD);
    tc_gemm<0, 1, 0><<<dim3(8, 32), blk, GSMEM>>>(hb, w2r, b2, o1, t, MM, DD, FF);
    ln_kernel<<<MM, blk>>>(t, g2, be2, out, nullptr);
}

// round 10
// speedup vs baseline: 4.5832x; 1.1205x over previous
#include <cuda_runtime.h>
#include <cuda_bf16.h>
#include <math.h>
#include <stdint.h>

// Problem constants
#define BB 2
#define SS 2048
#define DD 1024
#define HH 16
#define DH 64
#define MM (BB * SS)          // 4096 rows
#define FF (4 * DD)           // 4096 ffn hidden
#define EPS 1e-5f

// ---------------------------------------------------------------------------
// Scratch (static device memory — allocation-free)
// ---------------------------------------------------------------------------
__device__ float g_q[MM * DD];
__device__ float g_k[MM * DD];
__device__ float g_v[MM * DD];
__device__ float g_vt[MM * DD];    // V transposed per batch: [b*DD + c][s]
__device__ float g_z[MM * DD];     // attn out (tf32-rounded at write)
__device__ float g_t[MM * DD];     // LN inputs (reused)
__device__ float g_o1[MM * DD];    // LN1 output exact (residual)
__device__ float g_o1r[MM * DD];   // LN1 output tf32-rounded (GEMM A)
__device__ float g_h[MM * FF];     // ffn hidden (tf32-rounded in epilogue)
// pre-rounded operands
__device__ float g_embr[MM * DD];
__device__ float g_wqr[DD * DD];
__device__ float g_wkr[DD * DD];
__device__ float g_wvr[DD * DD];
__device__ float g_w0r[DD * DD];
__device__ float g_w1r[FF * DD];
__device__ float g_w2r[FF * DD];

// ---------------------------------------------------------------------------
// Helpers
// ---------------------------------------------------------------------------
__device__ __forceinline__ uint32_t tf32u(float x) {
    uint32_t u = __float_as_uint(x), r;
    asm("cvt.rna.tf32.f32 %0, %1;" : "=r"(r) : "r"(u));
    return r;
}
__device__ __forceinline__ float tf32r(float x) {
    return __uint_as_float(tf32u(x));
}
__device__ __forceinline__ uint32_t su32(const void* p) {
    return (uint32_t)__cvta_generic_to_shared(p);
}
__device__ __forceinline__ void ldsm_x4(uint32_t* r, uint32_t addr) {
    asm volatile("ldmatrix.sync.aligned.m8n8.x4.shared.b16 {%0,%1,%2,%3}, [%4];"
                 : "=r"(r[0]), "=r"(r[1]), "=r"(r[2]), "=r"(r[3]) : "r"(addr));
}
__device__ __forceinline__ void mma_tf32(float* d, const uint32_t* a,
                                         const uint32_t b0, const uint32_t b1) {
    asm volatile(
        "mma.sync.aligned.m16n8k8.row.col.f32.tf32.tf32.f32 "
        "{%0,%1,%2,%3}, {%4,%5,%6,%7}, {%8,%9}, {%0,%1,%2,%3};"
        : "+f"(d[0]), "+f"(d[1]), "+f"(d[2]), "+f"(d[3])
        : "r"(a[0]), "r"(a[1]), "r"(a[2]), "r"(a[3]), "r"(b0), "r"(b1));
}
#define CPA16(dst, src) \
    asm volatile("cp.async.cg.shared.global [%0], [%1], 16;" :: "r"(dst), "l"(src))
#define CPCOMMIT() asm volatile("cp.async.commit_group;" ::: "memory")
#define CPWAIT(n)  asm volatile("cp.async.wait_group %0;" :: "n"(n) : "memory")

// SW128 swizzle on byte offsets (rows of 128B): chunk' = chunk ^ (row%8)
#define SWZ(x) ((x) ^ (((x) >> 3) & 0x70))

// ---------------------------------------------------------------------------
// GEMM core. Stage = A 16KB + B 16KB = 32KB. 2 stages = 64KB -> 2 CTAs/SM.
// ---------------------------------------------------------------------------
#define GSMEM (2 * 32768)

#define GEMM_ISSUE_STAGE(st, kt, Ap, Bp)                                        \
    do {                                                                        \
        const uint32_t _sA = sbase + (uint32_t)(st) * 32768u;                   \
        const uint32_t _sB = _sA + 16384u;                                      \
        _Pragma("unroll")                                                       \
        for (int _i = 0; _i < 4; _i++) {                                        \
            int _id = _i * 256 + tid, _row = _id >> 3, _cc = _id & 7;           \
            uint32_t _off = (uint32_t)SWZ(_row * 128 + _cc * 16);               \
            CPA16(_sA + _off, (Ap) + (size_t)(bm + _row) * K + (kt) * 32 + _cc * 4); \
            CPA16(_sB + _off, (Bp) + (size_t)(bn + _row) * K + (kt) * 32 + _cc * 4); \
        }                                                                       \
    } while (0)

#define GEMM_COMPUTE_STAGE(st)                                                  \
    do {                                                                        \
        const uint32_t abase = sbase + (uint32_t)(st) * 32768u;                 \
        const uint32_t bbase = abase + 16384u;                                  \
        _Pragma("unroll")                                                       \
        for (int s = 0; s < 4; s++) {                                           \
            const uint32_t ca = (uint32_t)((((s << 1) | ha) ^ r8) << 4);        \
            const uint32_t cb = (uint32_t)((((s << 1) | hb) ^ r8) << 4);        \
            uint32_t af[4][4], bf[2][4];                                        \
            _Pragma("unroll")                                                   \
            for (int m = 0; m < 4; m++) ldsm_x4(af[m], abase + aRow[m] + ca);   \
            _Pragma("unroll")                                                   \
            for (int p = 0; p < 2; p++) ldsm_x4(bf[p], bbase + bRow[p] + cb);   \
            _Pragma("unroll")                                                   \
            for (int m = 0; m < 4; m++) {                                       \
                _Pragma("unroll")                                               \
                for (int nt = 0; nt < 4; nt++) {                                \
                    const int p = nt >> 1, e = (nt & 1) * 2;                    \
                    mma_tf32(acc[m][nt], af[m], bf[p][e], bf[p][e + 1]);        \
                }                                                               \
            }                                                                   \
        }                                                                       \
    } while (0)

#define GEMM_PREAMBLE()                                                         \
    const int tid = threadIdx.x;                                                \
    const int lane = tid & 31, wid = tid >> 5;                                  \
    const int wm = (wid >> 2) * 64;                                             \
    const int wn = (wid & 3) * 32;                                              \
    const int q = lane >> 3, r8 = lane & 7;                                     \
    const int ha = q >> 1;                                                      \
    const int hb = q & 1;                                                       \
    const uint32_t sbase = su32(smem);                                          \
    uint32_t aRow[4], bRow[2];                                                  \
    _Pragma("unroll")                                                           \
    for (int m = 0; m < 4; m++)                                                 \
        aRow[m] = (uint32_t)((wm + m * 16 + (q & 1) * 8 + r8) * 128);           \
    _Pragma("unroll")                                                           \
    for (int p = 0; p < 2; p++)                                                 \
        bRow[p] = (uint32_t)((wn + p * 16 + (q >> 1) * 8 + r8) * 128);          \
    float acc[4][4][4];                                                         \
    _Pragma("unroll")                                                           \
    for (int m = 0; m < 4; m++)                                                 \
        _Pragma("unroll")                                                       \
        for (int n = 0; n < 4; n++)                                             \
            _Pragma("unroll")                                                   \
            for (int e = 0; e < 4; e++) acc[m][n][e] = 0.f;

// 2-stage ring, 1 cp.async group in flight. Iter kt: wait(0) makes stage kt
// resident; barrier; prefetch stage kt+1 into the other buffer (its previous
// compute finished at iter kt-1, before this barrier -> WAR safe); compute.
#define GEMM_MAINLOOP(Ap, Bp)                                                   \
    const int nk = K / 32;                                                      \
    GEMM_ISSUE_STAGE(0, 0, Ap, Bp);                                             \
    CPCOMMIT();                                                                 \
    for (int kt = 0; kt < nk; kt++) {                                           \
        CPWAIT(0);                                                              \
        __syncthreads();                                                        \
        if (kt + 1 < nk) GEMM_ISSUE_STAGE((kt + 1) & 1, kt + 1, Ap, Bp);        \
        CPCOMMIT();                                                             \
        GEMM_COMPUTE_STAGE(kt & 1);                                             \
    }

#define GEMM_EPILOGUE(Cp, biasp, resp, RELU, RES, ROUND)                        \
    do {                                                                        \
        const int gid = lane >> 2, tig = lane & 3;                              \
        _Pragma("unroll")                                                       \
        for (int m = 0; m < 4; m++) {                                           \
            _Pragma("unroll")                                                   \
            for (int hf = 0; hf < 2; hf++) {                                    \
                const int row = bm + wm + m * 16 + gid + hf * 8;                \
                _Pragma("unroll")                                               \
                for (int nt = 0; nt < 4; nt++) {                                \
                    const int col = bn + wn + nt * 8 + tig * 2;                 \
                    const size_t idx = (size_t)row * N + col;                   \
                    float2 bi = *(const float2*)((biasp) + col);                \
                    float o0 = acc[m][nt][hf * 2 + 0] + bi.x;                   \
                    float o1 = acc[m][nt][hf * 2 + 1] + bi.y;                   \
                    if (RELU) { o0 = fmaxf(o0, 0.f); o1 = fmaxf(o1, 0.f); }     \
                    if (RES) {                                                  \
                        float2 rr = *(const float2*)((resp) + idx);             \
                        o0 += rr.x; o1 += rr.y;                                 \
                    }                                                           \
                    if (ROUND) { o0 = tf32r(o0); o1 = tf32r(o1); }              \
                    *(float2*)((Cp) + idx) = make_float2(o0, o1);               \
                }                                                               \
            }                                                                   \
        }                                                                       \
    } while (0)

// ---------------------------------------------------------------------------
// Generic GEMM: C[M,N] = A[M,K] @ B[N,K]^T + bias (+ReLU/res/round).
// A, B pre-rounded tf32 in gmem.
// ---------------------------------------------------------------------------
template <int RELU, int RES, int ROUND>
__global__ __launch_bounds__(256, 2) void tc_gemm(
    const float* __restrict__ A, const float* __restrict__ B,
    const float* __restrict__ bias, const float* __restrict__ res,
    float* __restrict__ C, int M, int N, int K)
{
    extern __shared__ __align__(1024) char smem[];
    const int bm = blockIdx.y * 128, bn = blockIdx.x * 128;
    GEMM_PREAMBLE();
    GEMM_MAINLOOP(A, B);
    GEMM_EPILOGUE(C, bias, res, RELU, RES, ROUND);
}

// ---------------------------------------------------------------------------
// Merged QKV GEMM
// ---------------------------------------------------------------------------
__global__ __launch_bounds__(256, 2) void tc_gemm_qkv(
    const float* __restrict__ A,
    const float* __restrict__ Wq, const float* __restrict__ Wk,
    const float* __restrict__ Wv,
    const float* __restrict__ bq, const float* __restrict__ bk,
    const float* __restrict__ bv,
    float* __restrict__ Cq, float* __restrict__ Ck, float* __restrict__ Cv)
{
    extern __shared__ __align__(1024) char smem[];
    const int N = DD, K = DD;
    const int sel = blockIdx.x >> 3;
    const int bm = blockIdx.y * 128, bn = (blockIdx.x & 7) * 128;
    const float* B = (sel == 0) ? Wq : (sel == 1) ? Wk : Wv;
    const float* bias = (sel == 0) ? bq : (sel == 1) ? bk : bv;
    float* C = (sel == 0) ? Cq : (sel == 1) ? Ck : Cv;
    GEMM_PREAMBLE();
    GEMM_MAINLOOP(A, B);
    GEMM_EPILOGUE(C, bias, (const float*)nullptr, 0, 0, 1);
}

// ---------------------------------------------------------------------------
// One merged tf32 rounding pass over all 7 operand segments.
//   emb 1M | Wq .25M | Wk .25M | Wv .25M | W0 .25M | W1 1M | W2 1M = 4.25M f4
// ---------------------------------------------------------------------------
#define RN_EMB (MM * DD / 4)
#define RN_WD  (DD * DD / 4)
#define RN_WF  (FF * DD / 4)
#define RN_TOTAL (RN_EMB + 4 * RN_WD + 2 * RN_WF)

__global__ __launch_bounds__(256) void round_all_kernel(
    const float4* __restrict__ emb, const float4* __restrict__ wq,
    const float4* __restrict__ wk, const float4* __restrict__ wv,
    const float4* __restrict__ w0, const float4* __restrict__ w1,
    const float4* __restrict__ w2,
    float4* __restrict__ embr, float4* __restrict__ wqr,
    float4* __restrict__ wkr, float4* __restrict__ wvr,
    float4* __restrict__ w0r, float4* __restrict__ w1r,
    float4* __restrict__ w2r)
{
    int i = blockIdx.x * blockDim.x + threadIdx.x;
    if (i >= RN_TOTAL) return;
    const float4* s; float4* d; int off = i;
    if (off < RN_EMB) { s = emb; d = embr; }
    else {
        off -= RN_EMB;
        if (off < RN_WD) { s = wq; d = wqr; }
        else { off -= RN_WD;
            if (off < RN_WD) { s = wk; d = wkr; }
            else { off -= RN_WD;
                if (off < RN_WD) { s = wv; d = wvr; }
                else { off -= RN_WD;
                    if (off < RN_WD) { s = w0; d = w0r; }
                    else { off -= RN_WD;
                        if (off < RN_WF) { s = w1; d = w1r; }
                        else { off -= RN_WF; s = w2; d = w2r; }
                    }
                }
            }
        }
    }
    float4 v = s[off];
    v.x = tf32r(v.x); v.y = tf32r(v.y); v.z = tf32r(v.z); v.w = tf32r(v.w);
    d[off] = v;
}

// ---------------------------------------------------------------------------
// V transpose: g_v [b*SS+s][c] -> g_vt [b*DD + c][s]
// ---------------------------------------------------------------------------
__global__ __launch_bounds__(256) void transpose_v(
    const float* __restrict__ v, float* __restrict__ vt)
{
    __shared__ float tile[32][33];
    const int tx = threadIdx.x, ty = threadIdx.y;
    const int s0 = blockIdx.x * 32, c0 = blockIdx.y * 32, b = blockIdx.z;
    const float* vb = v + (size_t)b * SS * DD;
    float* vtb = vt + (size_t)b * DD * SS;
#pragma unroll
    for (int i = 0; i < 4; i++)
        tile[ty + i * 8][tx] = vb[(size_t)(s0 + ty + i * 8) * DD + c0 + tx];
    __syncthreads();
#pragma unroll
    for (int i = 0; i < 4; i++)
        vtb[(size_t)(c0 + ty + i * 8) * SS + s0 + tx] = tile[tx][ty + i * 8];
}

// ---------------------------------------------------------------------------
// tf32 mma flash attention (unchanged from R7-passing version)
// ---------------------------------------------------------------------------
#define ASMEM (16384 + 2 * 16384 + 2 * 16384)   // Q + K[2] + Vt[2] = 80KB

__global__ __launch_bounds__(128) void attn_mma(
    const float* __restrict__ Q, const float* __restrict__ K,
    const float* __restrict__ Vt, float* __restrict__ O)
{
    extern __shared__ __align__(1024) char asm_[];
    const int tid = threadIdx.x, lane = tid & 31, w = tid >> 5;
    const int q2 = lane >> 3, r8 = lane & 7;
    const int gid = lane >> 2, tig = lane & 3;
    const int b = blockIdx.z, h = blockIdx.y, qb = blockIdx.x * 64;

    const uint32_t sb = su32(asm_);
    const uint32_t qs = sb;
    const uint32_t ks = sb + 16384;
    const uint32_t vs = sb + 49152;

    const float* Qg = Q + ((size_t)(b * SS + qb)) * DD + h * DH;
    const float* Kg = K + ((size_t)b * SS) * DD + h * DH;
    const float* Vg = Vt + ((size_t)(b * DD + h * DH)) * SS;

#pragma unroll
    for (int i = 0; i < 8; i++) {
        int id = i * 128 + tid, row = id >> 4, c = id & 15;
        CPA16(qs + row * 256 + ((c ^ (row & 7)) << 4),
              Qg + (size_t)row * DD + c * 4);
    }
    CPCOMMIT();
#pragma unroll
    for (int i = 0; i < 8; i++) {
        int id = i * 128 + tid, row = id >> 4, c = id & 15;
        uint32_t soff = row * 256 + ((c ^ (row & 7)) << 4);
        CPA16(ks + soff, Kg + (size_t)row * DD + c * 4);
        CPA16(vs + soff, Vg + (size_t)row * SS + c * 4);
    }
    CPCOMMIT();

    CPWAIT(1);
    __syncthreads();

    uint32_t qf[8][4];
    {
        const uint32_t aRow = (uint32_t)((w * 16 + (q2 & 1) * 8 + r8) * 256);
#pragma unroll
        for (int s = 0; s < 8; s++)
            ldsm_x4(qf[s], qs + aRow + ((((s << 1) | (q2 >> 1)) ^ r8) << 4));
    }

    float oacc[8][4];
#pragma unroll
    for (int nt = 0; nt < 8; nt++)
#pragma unroll
        for (int e = 0; e < 4; e++) oacc[nt][e] = 0.f;
    float mrow[2] = {-1e30f, -1e30f};
    float lrow[2] = {0.f, 0.f};

    const uint32_t bRowOff = (uint32_t)(((q2 >> 1) * 8 + r8) * 256);
    const uint32_t hbb = (uint32_t)(q2 & 1);
    const int src0 = (lane & ~3) | (tig >> 1);
    const int src1 = src0 | 2;
    const bool odd = (tig & 1) != 0;

    const int NT = SS / 64;
    for (int t = 0; t < NT; t++) {
        const uint32_t kb_ = ks + (t & 1) * 16384u;
        const uint32_t vb_ = vs + (t & 1) * 16384u;

        if (t + 1 < NT) {
            const int kb = (t + 1) * 64;
            const uint32_t kd = ks + ((t + 1) & 1) * 16384u;
            const uint32_t vd = vs + ((t + 1) & 1) * 16384u;
#pragma unroll
            for (int i = 0; i < 8; i++) {
                int id = i * 128 + tid, row = id >> 4, c = id & 15;
                uint32_t soff = row * 256 + ((c ^ (row & 7)) << 4);
                CPA16(kd + soff, Kg + (size_t)(kb + row) * DD + c * 4);
                CPA16(vd + soff, Vg + (size_t)row * SS + kb + c * 4);
            }
            CPCOMMIT();
            CPWAIT(1);
        } else {
            CPWAIT(0);
        }
        __syncthreads();

        float sacc[8][4];
#pragma unroll
        for (int nt = 0; nt < 8; nt++)
#pragma unroll
            for (int e = 0; e < 4; e++) sacc[nt][e] = 0.f;
#pragma unroll
        for (int s = 0; s < 8; s++) {
            uint32_t kf[4][4];
            const uint32_t cb = ((((uint32_t)s << 1) | hbb) ^ r8) << 4;
#pragma unroll
            for (int p = 0; p < 4; p++)
                ldsm_x4(kf[p], kb_ + bRowOff + p * 4096u + cb);
#pragma unroll
            for (int nt = 0; nt < 8; nt++)
                mma_tf32(sacc[nt], qf[s], kf[nt >> 1][(nt & 1) * 2],
                         kf[nt >> 1][(nt & 1) * 2 + 1]);
        }

#pragma unroll
        for (int hh = 0; hh < 2; hh++) {
            float mx = -1e30f;
#pragma unroll
            for (int nt = 0; nt < 8; nt++)
                mx = fmaxf(mx, fmaxf(sacc[nt][hh * 2], sacc[nt][hh * 2 + 1]));
            mx = fmaxf(mx, __shfl_xor_sync(0xffffffffu, mx, 1));
            mx = fmaxf(mx, __shfl_xor_sync(0xffffffffu, mx, 2));
            const float mn = fmaxf(mrow[hh], mx);
            const float sc = __expf(mrow[hh] - mn);
            float sum = 0.f;
#pragma unroll
            for (int nt = 0; nt < 8; nt++) {
                float p0 = __expf(sacc[nt][hh * 2] - mn);
                float p1 = __expf(sacc[nt][hh * 2 + 1] - mn);
                sacc[nt][hh * 2] = p0;
                sacc[nt][hh * 2 + 1] = p1;
                sum += p0 + p1;
            }
            sum += __shfl_xor_sync(0xffffffffu, sum, 1);
            sum += __shfl_xor_sync(0xffffffffu, sum, 2);
            lrow[hh] = lrow[hh] * sc + sum;
            mrow[hh] = mn;
#pragma unroll
            for (int nt = 0; nt < 8; nt++) {
                oacc[nt][hh * 2] *= sc;
                oacc[nt][hh * 2 + 1] *= sc;
            }
        }

        uint32_t pf[8][4];
#pragma unroll
        for (int t8 = 0; t8 < 8; t8++) {
            uint32_t c0 = tf32u(sacc[t8][0]);
            uint32_t c1 = tf32u(sacc[t8][1]);
            uint32_t c2 = tf32u(sacc[t8][2]);
            uint32_t c3 = tf32u(sacc[t8][3]);
            uint32_t u00 = __shfl_sync(0xffffffffu, c0, src0);
            uint32_t u01 = __shfl_sync(0xffffffffu, c1, src0);
            uint32_t u10 = __shfl_sync(0xffffffffu, c2, src0);
            uint32_t u11 = __shfl_sync(0xffffffffu, c3, src0);
            uint32_t u20 = __shfl_sync(0xffffffffu, c0, src1);
            uint32_t u21 = __shfl_sync(0xffffffffu, c1, src1);
            uint32_t u30 = __shfl_sync(0xffffffffu, c2, src1);
            uint32_t u31 = __shfl_sync(0xffffffffu, c3, src1);
            pf[t8][0] = odd ? u01 : u00;
            pf[t8][1] = odd ? u11 : u10;
            pf[t8][2] = odd ? u21 : u20;
            pf[t8][3] = odd ? u31 : u30;
        }

#pragma unroll
        for (int t8 = 0; t8 < 8; t8++) {
            uint32_t vf[4][4];
            const uint32_t cb = ((((uint32_t)t8 << 1) | hbb) ^ r8) << 4;
#pragma unroll
            for (int p = 0; p < 4; p++)
                ldsm_x4(vf[p], vb_ + bRowOff + p * 4096u + cb);
#pragma unroll
            for (int nt = 0; nt < 8; nt++)
                mma_tf32(oacc[nt], pf[t8], vf[nt >> 1][(nt & 1) * 2],
                         vf[nt >> 1][(nt & 1) * 2 + 1]);
        }
        __syncthreads();
    }

    float* Og = O + ((size_t)(b * SS + qb)) * DD + h * DH;
#pragma unroll
    for (int hh = 0; hh < 2; hh++) {
        const float invl = 0.125f / lrow[hh];
        const int row = w * 16 + gid + hh * 8;
#pragma unroll
        for (int nt = 0; nt < 8; nt++) {
            const int col = nt * 8 + tig * 2;
            *(float2*)(Og + (size_t)row * DD + col) =
                make_float2(tf32r(oacc[nt][hh * 2] * invl),
                            tf32r(oacc[nt][hh * 2 + 1] * invl));
        }
    }
}

// ---------------------------------------------------------------------------
// LayerNorm over D=1024; optional tf32-rounded second copy
// ---------------------------------------------------------------------------
__global__ __launch_bounds__(256) void ln_kernel(
    const float* __restrict__ x, const float* __restrict__ g,
    const float* __restrict__ be, float* __restrict__ out,
    float* __restrict__ out_r)
{
    const int row = blockIdx.x;
    const int tid = threadIdx.x;
    const float* xr = x + (size_t)row * DD;

    float4 xv = *(const float4*)(xr + tid * 4);
    float sum = xv.x + xv.y + xv.z + xv.w;
    float sq = xv.x * xv.x + xv.y * xv.y + xv.z * xv.z + xv.w * xv.w;

    __shared__ float s1[32], s2[32];
#pragma unroll
    for (int o = 16; o > 0; o >>= 1) {
        sum += __shfl_xor_sync(0xffffffffu, sum, o);
        sq += __shfl_xor_sync(0xffffffffu, sq, o);
    }
    const int w = tid >> 5, l = tid & 31;
    if (l == 0) { s1[w] = sum; s2[w] = sq; }
    __syncthreads();
    if (w == 0) {
        sum = (l < 8) ? s1[l] : 0.f;
        sq = (l < 8) ? s2[l] : 0.f;
#pragma unroll
        for (int o = 4; o > 0; o >>= 1) {
            sum += __shfl_xor_sync(0xffffffffu, sum, o);
            sq += __shfl_xor_sync(0xffffffffu, sq, o);
        }
        if (l == 0) { s1[0] = sum; s2[0] = sq; }
    }
    __syncthreads();
    const float mu = s1[0] * (1.f / DD);
    const float var = s2[0] * (1.f / DD) - mu * mu;
    const float rstd = rsqrtf(var + EPS);

    float4 gv = *(const float4*)(g + tid * 4);
    float4 bv = *(const float4*)(be + tid * 4);
    float4 ov;
    ov.x = (xv.x - mu) * rstd * gv.x + bv.x;
    ov.y = (xv.y - mu) * rstd * gv.y + bv.y;
    ov.z = (xv.z - mu) * rstd * gv.z + bv.z;
    ov.w = (xv.w - mu) * rstd * gv.w + bv.w;
    *(float4*)(out + (size_t)row * DD + tid * 4) = ov;
    if (out_r) {
        float4 rv;
        rv.x = tf32r(ov.x); rv.y = tf32r(ov.y);
        rv.z = tf32r(ov.z); rv.w = tf32r(ov.w);
        *(float4*)(out_r + (size_t)row * DD + tid * 4) = rv;
    }
}

// ---------------------------------------------------------------------------
// Launch
// ---------------------------------------------------------------------------
extern "C" void kernel_launch(void* const* d_in, const int* in_sizes, int n_in,
                              void* d_out, int out_size)
{
    const float* emb = (const float*)d_in[0];
    const float* Wq  = (const float*)d_in[1];
    const float* bq  = (const float*)d_in[2];
    const float* Wk  = (const float*)d_in[3];
    const float* bk  = (const float*)d_in[4];
    const float* Wv  = (const float*)d_in[5];
    const float* bv  = (const float*)d_in[6];
    const float* W0  = (const float*)d_in[7];
    const float* b0  = (const float*)d_in[8];
    const float* g1  = (const float*)d_in[9];
    const float* be1 = (const float*)d_in[10];
    const float* W1  = (const float*)d_in[11];
    const float* b1  = (const float*)d_in[12];
    const float* W2  = (const float*)d_in[13];
    const float* b2  = (const float*)d_in[14];
    const float* g2  = (const float*)d_in[15];
    const float* be2 = (const float*)d_in[16];
    float* out = (float*)d_out;

    float *q, *k, *v, *vt, *z, *t, *o1, *o1r, *hb;
    float *embr, *wqr, *wkr, *wvr, *w0r, *w1r, *w2r;
    cudaGetSymbolAddress((void**)&q, g_q);
    cudaGetSymbolAddress((void**)&k, g_k);
    cudaGetSymbolAddress((void**)&v, g_v);
    cudaGetSymbolAddress((void**)&vt, g_vt);
    cudaGetSymbolAddress((void**)&z, g_z);
    cudaGetSymbolAddress((void**)&t, g_t);
    cudaGetSymbolAddress((void**)&o1, g_o1);
    cudaGetSymbolAddress((void**)&o1r, g_o1r);
    cudaGetSymbolAddress((void**)&hb, g_h);
    cudaGetSymbolAddress((void**)&embr, g_embr);
    cudaGetSymbolAddress((void**)&wqr, g_wqr);
    cudaGetSymbolAddress((void**)&wkr, g_wkr);
    cudaGetSymbolAddress((void**)&wvr, g_wvr);
    cudaGetSymbolAddress((void**)&w0r, g_w0r);
    cudaGetSymbolAddress((void**)&w1r, g_w1r);
    cudaGetSymbolAddress((void**)&w2r, g_w2r);

    cudaFuncSetAttribute(attn_mma,
                         cudaFuncAttributeMaxDynamicSharedMemorySize, ASMEM);
    cudaFuncSetAttribute(tc_gemm_qkv,
                         cudaFuncAttributeMaxDynamicSharedMemorySize, GSMEM);
    cudaFuncSetAttribute(tc_gemm<0, 1, 0>,
                         cudaFuncAttributeMaxDynamicSharedMemorySize, GSMEM);
    cudaFuncSetAttribute(tc_gemm<1, 0, 1>,
                         cudaFuncAttributeMaxDynamicSharedMemorySize, GSMEM);

    const dim3 blk(256);

    // one merged tf32 rounding pass for all operands
    round_all_kernel<<<(RN_TOTAL + 255) / 256, blk>>>(
        (const float4*)emb, (const float4*)Wq, (const float4*)Wk,
        (const float4*)Wv, (const float4*)W0, (const float4*)W1,
        (const float4*)W2,
        (float4*)embr, (float4*)wqr, (float4*)wkr, (float4*)wvr,
        (float4*)w0r, (float4*)w1r, (float4*)w2r);

    // QKV projections — one merged launch, outputs rounded
    tc_gemm_qkv<<<dim3(24, MM / 128), blk, GSMEM>>>(
        embr, wqr, wkr, wvr, bq, bk, bv, q, k, v);

    // V transpose for the PV mma
    transpose_v<<<dim3(SS / 32, DD / 32, BB), dim3(32, 8)>>>(v, vt);

    // attention -> z (concat-head layout, rounded)
    attn_mma<<<dim3(SS / 64, HH, BB), dim3(128), ASMEM>>>(q, k, vt, z);

    // W0 projection + residual(emb), then LN1 -> o1 (exact) / o1r (rounded)
    tc_gemm<0, 1, 0><<<dim3(8, 32), blk, GSMEM>>>(z, w0r, b0, emb, t, MM, DD, DD);
    ln_kernel<<<MM, blk>>>(t, g1, be1, o1, o1r);

    // FFN
    tc_gemm<1, 0, 1><<<dim3(32, 32), blk, GSMEM>>>(o1r, w1r, b1, nullptr, hb, MM, FF, DD);
    tc_gemm<0, 1, 0><<<dim3(8, 32), blk, GSMEM>>>(hb, w2r, b2, o1, t, MM, DD, FF);
    ln_kernel<<<MM, blk>>>(t, g2, be2, out, nullptr);
}

// round 11
// speedup vs baseline: 8.3779x; 1.8279x over previous
#include <cuda_runtime.h>
#include <cuda_fp16.h>
#include <math.h>
#include <stdint.h>

// Problem constants
#define BB 2
#define SS 2048
#define DD 1024
#define HH 16
#define DH 64
#define MM (BB * SS)          // 4096 rows
#define FF (4 * DD)           // 4096 ffn hidden
#define EPS 1e-5f

// ---------------------------------------------------------------------------
// Scratch (static device memory — allocation-free)
// ---------------------------------------------------------------------------
__device__ __half g_qh[MM * DD];
__device__ __half g_kh[MM * DD];
__device__ __half g_vh[MM * DD];
__device__ __half g_vth[MM * DD];   // V transposed per batch: [b*DD + c][s]
__device__ __half g_zh[MM * DD];    // attn out (fp16)
__device__ __half g_o1h[MM * DD];   // LN1 output fp16 (FFN1 A)
__device__ __half g_hh[MM * FF];    // ffn hidden fp16 (FFN2 A)
__device__ float  g_t[MM * DD];     // LN inputs (fp32, reused)
__device__ float  g_o1[MM * DD];    // LN1 output exact (residual)
// fp16 operand copies
__device__ __half g_embh[MM * DD];
__device__ __half g_wqh[DD * DD];
__device__ __half g_wkh[DD * DD];
__device__ __half g_wvh[DD * DD];
__device__ __half g_w0h[DD * DD];
__device__ __half g_w1h[FF * DD];
__device__ __half g_w2h[FF * DD];

// ---------------------------------------------------------------------------
// Helpers
// ---------------------------------------------------------------------------
__device__ __forceinline__ uint32_t su32(const void* p) {
    return (uint32_t)__cvta_generic_to_shared(p);
}
__device__ __forceinline__ uint32_t packh2(float lo, float hi) {
    __half2 h = __floats2half2_rn(lo, hi);
    return *reinterpret_cast<uint32_t*>(&h);
}
__device__ __forceinline__ void ldsm_x4(uint32_t* r, uint32_t addr) {
    asm volatile("ldmatrix.sync.aligned.m8n8.x4.shared.b16 {%0,%1,%2,%3}, [%4];"
                 : "=r"(r[0]), "=r"(r[1]), "=r"(r[2]), "=r"(r[3]) : "r"(addr));
}
__device__ __forceinline__ void mma_f16(float* d, const uint32_t* a,
                                        const uint32_t b0, const uint32_t b1) {
    asm volatile(
        "mma.sync.aligned.m16n8k16.row.col.f32.f16.f16.f32 "
        "{%0,%1,%2,%3}, {%4,%5,%6,%7}, {%8,%9}, {%0,%1,%2,%3};"
        : "+f"(d[0]), "+f"(d[1]), "+f"(d[2]), "+f"(d[3])
        : "r"(a[0]), "r"(a[1]), "r"(a[2]), "r"(a[3]), "r"(b0), "r"(b1));
}
#define CPA16(dst, src) \
    asm volatile("cp.async.cg.shared.global [%0], [%1], 16;" :: "r"(dst), "l"(src))
#define CPCOMMIT() asm volatile("cp.async.commit_group;" ::: "memory")
#define CPWAIT(n)  asm volatile("cp.async.wait_group %0;" :: "n"(n) : "memory")

// SW128 swizzle on byte offsets (rows of 128B): chunk' = chunk ^ (row%8)
#define SWZ(x) ((x) ^ (((x) >> 3) & 0x70))

// ---------------------------------------------------------------------------
// GEMM core (fp16). K-tile = 64 halves = 128B/row. Stage = A 16KB + B 16KB.
// 2 stages = 64KB -> 2 CTAs/SM. Byte layout identical to the validated tf32
// version; only the mma opcode and global element strides differ.
// ---------------------------------------------------------------------------
#define GSMEM (2 * 32768)

#define GEMM_ISSUE_STAGE(st, kt, Ap, Bp)                                        \
    do {                                                                        \
        const uint32_t _sA = sbase + (uint32_t)(st) * 32768u;                   \
        const uint32_t _sB = _sA + 16384u;                                      \
        _Pragma("unroll")                                                       \
        for (int _i = 0; _i < 4; _i++) {                                        \
            int _id = _i * 256 + tid, _row = _id >> 3, _cc = _id & 7;           \
            uint32_t _off = (uint32_t)SWZ(_row * 128 + _cc * 16);               \
            CPA16(_sA + _off, (Ap) + (size_t)(bm + _row) * K + (kt) * 64 + _cc * 8); \
            CPA16(_sB + _off, (Bp) + (size_t)(bn + _row) * K + (kt) * 64 + _cc * 8); \
        }                                                                       \
    } while (0)

#define GEMM_COMPUTE_STAGE(st)                                                  \
    do {                                                                        \
        const uint32_t abase = sbase + (uint32_t)(st) * 32768u;                 \
        const uint32_t bbase = abase + 16384u;                                  \
        _Pragma("unroll")                                                       \
        for (int s = 0; s < 4; s++) {                                           \
            const uint32_t ca = (uint32_t)((((s << 1) | ha) ^ r8) << 4);        \
            const uint32_t cb = (uint32_t)((((s << 1) | hb) ^ r8) << 4);        \
            uint32_t af[4][4], bf[2][4];                                        \
            _Pragma("unroll")                                                   \
            for (int m = 0; m < 4; m++) ldsm_x4(af[m], abase + aRow[m] + ca);   \
            _Pragma("unroll")                                                   \
            for (int p = 0; p < 2; p++) ldsm_x4(bf[p], bbase + bRow[p] + cb);   \
            _Pragma("unroll")                                                   \
            for (int m = 0; m < 4; m++) {                                       \
                _Pragma("unroll")                                               \
                for (int nt = 0; nt < 4; nt++) {                                \
                    const int p = nt >> 1, e = (nt & 1) * 2;                    \
                    mma_f16(acc[m][nt], af[m], bf[p][e], bf[p][e + 1]);         \
                }                                                               \
            }                                                                   \
        }                                                                       \
    } while (0)

#define GEMM_PREAMBLE()                                                         \
    const int tid = threadIdx.x;                                                \
    const int lane = tid & 31, wid = tid >> 5;                                  \
    const int wm = (wid >> 2) * 64;                                             \
    const int wn = (wid & 3) * 32;                                              \
    const int q = lane >> 3, r8 = lane & 7;                                     \
    const int ha = q >> 1;                                                      \
    const int hb = q & 1;                                                       \
    const uint32_t sbase = su32(smem);                                          \
    uint32_t aRow[4], bRow[2];                                                  \
    _Pragma("unroll")                                                           \
    for (int m = 0; m < 4; m++)                                                 \
        aRow[m] = (uint32_t)((wm + m * 16 + (q & 1) * 8 + r8) * 128);           \
    _Pragma("unroll")                                                           \
    for (int p = 0; p < 2; p++)                                                 \
        bRow[p] = (uint32_t)((wn + p * 16 + (q >> 1) * 8 + r8) * 128);          \
    float acc[4][4][4];                                                         \
    _Pragma("unroll")                                                           \
    for (int m = 0; m < 4; m++)                                                 \
        _Pragma("unroll")                                                       \
        for (int n = 0; n < 4; n++)                                             \
            _Pragma("unroll")                                                   \
            for (int e = 0; e < 4; e++) acc[m][n][e] = 0.f;

// 2-stage ring, 1 cp.async group in flight (R10-validated pattern).
#define GEMM_MAINLOOP(Ap, Bp)                                                   \
    const int nk = K / 64;                                                      \
    GEMM_ISSUE_STAGE(0, 0, Ap, Bp);                                             \
    CPCOMMIT();                                                                 \
    for (int kt = 0; kt < nk; kt++) {                                           \
        CPWAIT(0);                                                              \
        __syncthreads();                                                        \
        if (kt + 1 < nk) GEMM_ISSUE_STAGE((kt + 1) & 1, kt + 1, Ap, Bp);        \
        CPCOMMIT();                                                             \
        GEMM_COMPUTE_STAGE(kt & 1);                                             \
    }

// HOUT=1: write __half2 into Ch. HOUT=0: write float2 into C (+res optional).
#define GEMM_EPILOGUE(Cp, Chp, biasp, resp, RELU, RES, HOUT)                    \
    do {                                                                        \
        const int gid = lane >> 2, tig = lane & 3;                              \
        _Pragma("unroll")                                                       \
        for (int m = 0; m < 4; m++) {                                           \
            _Pragma("unroll")                                                   \
            for (int hf = 0; hf < 2; hf++) {                                    \
                const int row = bm + wm + m * 16 + gid + hf * 8;                \
                _Pragma("unroll")                                               \
                for (int nt = 0; nt < 4; nt++) {                                \
                    const int col = bn + wn + nt * 8 + tig * 2;                 \
                    const size_t idx = (size_t)row * N + col;                   \
                    float2 bi = *(const float2*)((biasp) + col);                \
                    float o0 = acc[m][nt][hf * 2 + 0] + bi.x;                   \
                    float o1 = acc[m][nt][hf * 2 + 1] + bi.y;                   \
                    if (RELU) { o0 = fmaxf(o0, 0.f); o1 = fmaxf(o1, 0.f); }     \
                    if (RES) {                                                  \
                        float2 rr = *(const float2*)((resp) + idx);             \
                        o0 += rr.x; o1 += rr.y;                                 \
                    }                                                           \
                    if (HOUT) {                                                 \
                        *(uint32_t*)((Chp) + idx) = packh2(o0, o1);             \
                    } else {                                                    \
                        *(float2*)((Cp) + idx) = make_float2(o0, o1);           \
                    }                                                           \
                }                                                               \
            }                                                                   \
        }                                                                       \
    } while (0)

// ---------------------------------------------------------------------------
// Generic fp16 GEMM: C = A[M,K] @ B[N,K]^T + bias (+ReLU/res), out fp32 or fp16
// ---------------------------------------------------------------------------
template <int RELU, int RES, int HOUT>
__global__ __launch_bounds__(256, 2) void tc_gemm(
    const __half* __restrict__ A, const __half* __restrict__ B,
    const float* __restrict__ bias, const float* __restrict__ res,
    float* __restrict__ C, __half* __restrict__ Ch, int M, int N, int K)
{
    extern __shared__ __align__(1024) char smem[];
    const int bm = blockIdx.y * 128, bn = blockIdx.x * 128;
    GEMM_PREAMBLE();
    GEMM_MAINLOOP(A, B);
    GEMM_EPILOGUE(C, Ch, bias, res, RELU, RES, HOUT);
}

// ---------------------------------------------------------------------------
// Merged QKV GEMM — fp16 outputs
// ---------------------------------------------------------------------------
__global__ __launch_bounds__(256, 2) void tc_gemm_qkv(
    const __half* __restrict__ A,
    const __half* __restrict__ Wq, const __half* __restrict__ Wk,
    const __half* __restrict__ Wv,
    const float* __restrict__ bq, const float* __restrict__ bk,
    const float* __restrict__ bv,
    __half* __restrict__ Cq, __half* __restrict__ Ck, __half* __restrict__ Cv)
{
    extern __shared__ __align__(1024) char smem[];
    const int N = DD, K = DD;
    const int sel = blockIdx.x >> 3;
    const int bm = blockIdx.y * 128, bn = (blockIdx.x & 7) * 128;
    const __half* B = (sel == 0) ? Wq : (sel == 1) ? Wk : Wv;
    const float* bias = (sel == 0) ? bq : (sel == 1) ? bk : bv;
    __half* Ch = (sel == 0) ? Cq : (sel == 1) ? Ck : Cv;
    GEMM_PREAMBLE();
    GEMM_MAINLOOP(A, B);
    GEMM_EPILOGUE((float*)nullptr, Ch, bias, (const float*)nullptr, 0, 0, 1);
}

// ---------------------------------------------------------------------------
// One merged fp32->fp16 conversion pass over all 7 operand segments.
//   emb 1M | Wq .25M | Wk .25M | Wv .25M | W0 .25M | W1 1M | W2 1M = 4.25M f4
// ---------------------------------------------------------------------------
#define RN_EMB (MM * DD / 4)
#define RN_WD  (DD * DD / 4)
#define RN_WF  (FF * DD / 4)
#define RN_TOTAL (RN_EMB + 4 * RN_WD + 2 * RN_WF)

__global__ __launch_bounds__(256) void convert_all_kernel(
    const float4* __restrict__ emb, const float4* __restrict__ wq,
    const float4* __restrict__ wk, const float4* __restrict__ wv,
    const float4* __restrict__ w0, const float4* __restrict__ w1,
    const float4* __restrict__ w2,
    __half* __restrict__ embh, __half* __restrict__ wqh,
    __half* __restrict__ wkh, __half* __restrict__ wvh,
    __half* __restrict__ w0h, __half* __restrict__ w1h,
    __half* __restrict__ w2h)
{
    int i = blockIdx.x * blockDim.x + threadIdx.x;
    if (i >= RN_TOTAL) return;
    const float4* s; __half* d; int off = i;
    if (off < RN_EMB) { s = emb; d = embh; }
    else {
        off -= RN_EMB;
        if (off < RN_WD) { s = wq; d = wqh; }
        else { off -= RN_WD;
            if (off < RN_WD) { s = wk; d = wkh; }
            else { off -= RN_WD;
                if (off < RN_WD) { s = wv; d = wvh; }
                else { off -= RN_WD;
                    if (off < RN_WD) { s = w0; d = w0h; }
                    else { off -= RN_WD;
                        if (off < RN_WF) { s = w1; d = w1h; }
                        else { off -= RN_WF; s = w2; d = w2h; }
                    }
                }
            }
        }
    }
    float4 v = s[off];
    uint2 o;
    o.x = packh2(v.x, v.y);
    o.y = packh2(v.z, v.w);
    *(uint2*)(d + (size_t)off * 4) = o;
}

// ---------------------------------------------------------------------------
// V transpose (fp16): g_vh [b*SS+s][c] -> g_vth [b*DD + c][s]
// ---------------------------------------------------------------------------
__global__ __launch_bounds__(256) void transpose_v(
    const __half* __restrict__ v, __half* __restrict__ vt)
{
    __shared__ __half tile[32][34];
    const int tx = threadIdx.x, ty = threadIdx.y;
    const int s0 = blockIdx.x * 32, c0 = blockIdx.y * 32, b = blockIdx.z;
    const __half* vb = v + (size_t)b * SS * DD;
    __half* vtb = vt + (size_t)b * DD * SS;
#pragma unroll
    for (int i = 0; i < 4; i++)
        tile[ty + i * 8][tx] = vb[(size_t)(s0 + ty + i * 8) * DD + c0 + tx];
    __syncthreads();
#pragma unroll
    for (int i = 0; i < 4; i++)
        vtb[(size_t)(c0 + ty + i * 8) * SS + s0 + tx] = tile[tx][ty + i * 8];
}

// ---------------------------------------------------------------------------
// fp16 mma flash attention. Per (b,h): BQ=64 (4 warps x m16), BK=64, DH=64.
// fp16 rows: 64 halves = 128B. S C-frag -> PV A-frag needs only cvt+pack
// (no shuffles). Tiles: Q 8KB + K[2] 16KB + Vt[2] 16KB = 40KB.
// ---------------------------------------------------------------------------
#define ASMEM (8192 + 2 * 8192 + 2 * 8192)

__global__ __launch_bounds__(128) void attn_mma(
    const __half* __restrict__ Q, const __half* __restrict__ K,
    const __half* __restrict__ Vt, __half* __restrict__ O)
{
    extern __shared__ __align__(1024) char asm_[];
    const int tid = threadIdx.x, lane = tid & 31, w = tid >> 5;
    const int q2 = lane >> 3, r8 = lane & 7;
    const int gid = lane >> 2, tig = lane & 3;
    const int b = blockIdx.z, h = blockIdx.y, qb = blockIdx.x * 64;

    const uint32_t sb = su32(asm_);
    const uint32_t qs = sb;
    const uint32_t ks = sb + 8192;
    const uint32_t vs = sb + 24576;

    const __half* Qg = Q + ((size_t)(b * SS + qb)) * DD + h * DH;
    const __half* Kg = K + ((size_t)b * SS) * DD + h * DH;
    const __half* Vg = Vt + ((size_t)(b * DD + h * DH)) * SS;

    // stage Q (group 0): 64 rows x 8 chunks of 16B
#pragma unroll
    for (int i = 0; i < 4; i++) {
        int id = i * 128 + tid, row = id >> 3, c = id & 7;
        CPA16(qs + row * 128 + ((c ^ (row & 7)) << 4),
              Qg + (size_t)row * DD + c * 8);
    }
    CPCOMMIT();
    // stage KV tile 0 (group 1)
#pragma unroll
    for (int i = 0; i < 4; i++) {
        int id = i * 128 + tid, row = id >> 3, c = id & 7;
        uint32_t soff = row * 128 + ((c ^ (row & 7)) << 4);
        CPA16(ks + soff, Kg + (size_t)row * DD + c * 8);
        CPA16(vs + soff, Vg + (size_t)row * SS + c * 8);
    }
    CPCOMMIT();

    CPWAIT(1);
    __syncthreads();

    // Q A-frags: 4 k16-steps over dh=64
    uint32_t qf[4][4];
    {
        const uint32_t aRow = (uint32_t)((w * 16 + (q2 & 1) * 8 + r8) * 128);
#pragma unroll
        for (int s = 0; s < 4; s++)
            ldsm_x4(qf[s], qs + aRow + ((((s << 1) | (q2 >> 1)) ^ r8) << 4));
    }

    float oacc[8][4];
#pragma unroll
    for (int nt = 0; nt < 8; nt++)
#pragma unroll
        for (int e = 0; e < 4; e++) oacc[nt][e] = 0.f;
    float mrow[2] = {-1e30f, -1e30f};
    float lrow[2] = {0.f, 0.f};

    const uint32_t bRowOff = (uint32_t)(((q2 >> 1) * 8 + r8) * 128);
    const uint32_t hbb = (uint32_t)(q2 & 1);

    const int NT = SS / 64;
    for (int t = 0; t < NT; t++) {
        const uint32_t kb_ = ks + (t & 1) * 8192u;
        const uint32_t vb_ = vs + (t & 1) * 8192u;

        if (t + 1 < NT) {
            const int kb = (t + 1) * 64;
            const uint32_t kd = ks + ((t + 1) & 1) * 8192u;
            const uint32_t vd = vs + ((t + 1) & 1) * 8192u;
#pragma unroll
            for (int i = 0; i < 4; i++) {
                int id = i * 128 + tid, row = id >> 3, c = id & 7;
                uint32_t soff = row * 128 + ((c ^ (row & 7)) << 4);
                CPA16(kd + soff, Kg + (size_t)(kb + row) * DD + c * 8);
                CPA16(vd + soff, Vg + (size_t)row * SS + kb + c * 8);
            }
            CPCOMMIT();
            CPWAIT(1);
        } else {
            CPWAIT(0);
        }
        __syncthreads();

        // ---- S = Q @ K^T  (16q x 64kv per warp; 4 k16-steps over dh) ----
        float sacc[8][4];
#pragma unroll
        for (int nt = 0; nt < 8; nt++)
#pragma unroll
            for (int e = 0; e < 4; e++) sacc[nt][e] = 0.f;
#pragma unroll
        for (int s = 0; s < 4; s++) {
            uint32_t kf[4][4];
            const uint32_t cb = ((((uint32_t)s << 1) | hbb) ^ r8) << 4;
#pragma unroll
            for (int p = 0; p < 4; p++)
                ldsm_x4(kf[p], kb_ + bRowOff + p * 2048u + cb);
#pragma unroll
            for (int nt = 0; nt < 8; nt++)
                mma_f16(sacc[nt], qf[s], kf[nt >> 1][(nt & 1) * 2],
                        kf[nt >> 1][(nt & 1) * 2 + 1]);
        }

        // ---- online softmax (rows gid, gid+8) ----
#pragma unroll
        for (int hh = 0; hh < 2; hh++) {
            float mx = -1e30f;
#pragma unroll
            for (int nt = 0; nt < 8; nt++)
                mx = fmaxf(mx, fmaxf(sacc[nt][hh * 2], sacc[nt][hh * 2 + 1]));
            mx = fmaxf(mx, __shfl_xor_sync(0xffffffffu, mx, 1));
            mx = fmaxf(mx, __shfl_xor_sync(0xffffffffu, mx, 2));
            const float mn = fmaxf(mrow[hh], mx);
            const float sc = __expf(mrow[hh] - mn);
            float sum = 0.f;
#pragma unroll
            for (int nt = 0; nt < 8; nt++) {
                float p0 = __expf(sacc[nt][hh * 2] - mn);
                float p1 = __expf(sacc[nt][hh * 2 + 1] - mn);
                sacc[nt][hh * 2] = p0;
                sacc[nt][hh * 2 + 1] = p1;
                sum += p0 + p1;
            }
            sum += __shfl_xor_sync(0xffffffffu, sum, 1);
            sum += __shfl_xor_sync(0xffffffffu, sum, 2);
            lrow[hh] = lrow[hh] * sc + sum;
            mrow[hh] = mn;
#pragma unroll
            for (int nt = 0; nt < 8; nt++) {
                oacc[nt][hh * 2] *= sc;
                oacc[nt][hh * 2 + 1] *= sc;
            }
        }

        // ---- P: C-frag -> fp16 A-frag via pack only (no shuffles) ----
        // PV k-step t8 covers kv 16*t8..16*t8+15 = S n8-tiles 2*t8, 2*t8+1.
        uint32_t pf[4][4];
#pragma unroll
        for (int t8 = 0; t8 < 4; t8++) {
            pf[t8][0] = packh2(sacc[2 * t8][0], sacc[2 * t8][1]);
            pf[t8][1] = packh2(sacc[2 * t8][2], sacc[2 * t8][3]);
            pf[t8][2] = packh2(sacc[2 * t8 + 1][0], sacc[2 * t8 + 1][1]);
            pf[t8][3] = packh2(sacc[2 * t8 + 1][2], sacc[2 * t8 + 1][3]);
        }

        // ---- O += P @ V  (4 k16-steps over kv; n = dh 64) ----
#pragma unroll
        for (int t8 = 0; t8 < 4; t8++) {
            uint32_t vf[4][4];
            const uint32_t cb = ((((uint32_t)t8 << 1) | hbb) ^ r8) << 4;
#pragma unroll
            for (int p = 0; p < 4; p++)
                ldsm_x4(vf[p], vb_ + bRowOff + p * 2048u + cb);
#pragma unroll
            for (int nt = 0; nt < 8; nt++)
                mma_f16(oacc[nt], pf[t8], vf[nt >> 1][(nt & 1) * 2],
                        vf[nt >> 1][(nt & 1) * 2 + 1]);
        }
        __syncthreads();
    }

    // ---- write O as fp16 (concat-head layout), scaled by 1/(l*sqrt(64)) ----
    __half* Og = O + ((size_t)(b * SS + qb)) * DD + h * DH;
#pragma unroll
    for (int hh = 0; hh < 2; hh++) {
        const float invl = 0.125f / lrow[hh];
        const int row = w * 16 + gid + hh * 8;
#pragma unroll
        for (int nt = 0; nt < 8; nt++) {
            const int col = nt * 8 + tig * 2;
            *(uint32_t*)(Og + (size_t)row * DD + col) =
                packh2(oacc[nt][hh * 2] * invl, oacc[nt][hh * 2 + 1] * invl);
        }
    }
}

// ---------------------------------------------------------------------------
// LayerNorm over D=1024; optional fp16 second copy
// ---------------------------------------------------------------------------
__global__ __launch_bounds__(256) void ln_kernel(
    const float* __restrict__ x, const float* __restrict__ g,
    const float* __restrict__ be, float* __restrict__ out,
    __half* __restrict__ out_h)
{
    const int row = blockIdx.x;
    const int tid = threadIdx.x;
    const float* xr = x + (size_t)row * DD;

    float4 xv = *(const float4*)(xr + tid * 4);
    float sum = xv.x + xv.y + xv.z + xv.w;
    float sq = xv.x * xv.x + xv.y * xv.y + xv.z * xv.z + xv.w * xv.w;

    __shared__ float s1[32], s2[32];
#pragma unroll
    for (int o = 16; o > 0; o >>= 1) {
        sum += __shfl_xor_sync(0xffffffffu, sum, o);
        sq += __shfl_xor_sync(0xffffffffu, sq, o);
    }
    const int w = tid >> 5, l = tid & 31;
    if (l == 0) { s1[w] = sum; s2[w] = sq; }
    __syncthreads();
    if (w == 0) {
        sum = (l < 8) ? s1[l] : 0.f;
        sq = (l < 8) ? s2[l] : 0.f;
#pragma unroll
        for (int o = 4; o > 0; o >>= 1) {
            sum += __shfl_xor_sync(0xffffffffu, sum, o);
            sq += __shfl_xor_sync(0xffffffffu, sq, o);
        }
        if (l == 0) { s1[0] = sum; s2[0] = sq; }
    }
    __syncthreads();
    const float mu = s1[0] * (1.f / DD);
    const float var = s2[0] * (1.f / DD) - mu * mu;
    const float rstd = rsqrtf(var + EPS);

    float4 gv = *(const float4*)(g + tid * 4);
    float4 bv = *(const float4*)(be + tid * 4);
    float4 ov;
    ov.x = (xv.x - mu) * rstd * gv.x + bv.x;
    ov.y = (xv.y - mu) * rstd * gv.y + bv.y;
    ov.z = (xv.z - mu) * rstd * gv.z + bv.z;
    ov.w = (xv.w - mu) * rstd * gv.w + bv.w;
    *(float4*)(out + (size_t)row * DD + tid * 4) = ov;
    if (out_h) {
        uint2 o;
        o.x = packh2(ov.x, ov.y);
        o.y = packh2(ov.z, ov.w);
        *(uint2*)(out_h + (size_t)row * DD + tid * 4) = o;
    }
}

// ---------------------------------------------------------------------------
// Launch
// ---------------------------------------------------------------------------
extern "C" void kernel_launch(void* const* d_in, const int* in_sizes, int n_in,
                              void* d_out, int out_size)
{
    const float* emb = (const float*)d_in[0];
    const float* Wq  = (const float*)d_in[1];
    const float* bq  = (const float*)d_in[2];
    const float* Wk  = (const float*)d_in[3];
    const float* bk  = (const float*)d_in[4];
    const float* Wv  = (const float*)d_in[5];
    const float* bv  = (const float*)d_in[6];
    const float* W0  = (const float*)d_in[7];
    const float* b0  = (const float*)d_in[8];
    const float* g1  = (const float*)d_in[9];
    const float* be1 = (const float*)d_in[10];
    const float* W1  = (const float*)d_in[11];
    const float* b1  = (const float*)d_in[12];
    const float* W2  = (const float*)d_in[13];
    const float* b2  = (const float*)d_in[14];
    const float* g2  = (const float*)d_in[15];
    const float* be2 = (const float*)d_in[16];
    float* out = (float*)d_out;

    __half *qh, *kh, *vh, *vth, *zh, *o1h, *hh;
    __half *embh, *wqh, *wkh, *wvh, *w0h, *w1h, *w2h;
    float *t, *o1;
    cudaGetSymbolAddress((void**)&qh, g_qh);
    cudaGetSymbolAddress((void**)&kh, g_kh);
    cudaGetSymbolAddress((void**)&vh, g_vh);
    cudaGetSymbolAddress((void**)&vth, g_vth);
    cudaGetSymbolAddress((void**)&zh, g_zh);
    cudaGetSymbolAddress((void**)&o1h, g_o1h);
    cudaGetSymbolAddress((void**)&hh, g_hh);
    cudaGetSymbolAddress((void**)&t, g_t);
    cudaGetSymbolAddress((void**)&o1, g_o1);
    cudaGetSymbolAddress((void**)&embh, g_embh);
    cudaGetSymbolAddress((void**)&wqh, g_wqh);
    cudaGetSymbolAddress((void**)&wkh, g_wkh);
    cudaGetSymbolAddress((void**)&wvh, g_wvh);
    cudaGetSymbolAddress((void**)&w0h, g_w0h);
    cudaGetSymbolAddress((void**)&w1h, g_w1h);
    cudaGetSymbolAddress((void**)&w2h, g_w2h);

    cudaFuncSetAttribute(attn_mma,
                         cudaFuncAttributeMaxDynamicSharedMemorySize, ASMEM);
    cudaFuncSetAttribute(tc_gemm_qkv,
                         cudaFuncAttributeMaxDynamicSharedMemorySize, GSMEM);
    cudaFuncSetAttribute(tc_gemm<0, 1, 0>,
                         cudaFuncAttributeMaxDynamicSharedMemorySize, GSMEM);
    cudaFuncSetAttribute(tc_gemm<1, 0, 1>,
                         cudaFuncAttributeMaxDynamicSharedMemorySize, GSMEM);

    const dim3 blk(256);

    // one merged fp32->fp16 conversion pass for all operands
    convert_all_kernel<<<(RN_TOTAL + 255) / 256, blk>>>(
        (const float4*)emb, (const float4*)Wq, (const float4*)Wk,
        (const float4*)Wv, (const float4*)W0, (const float4*)W1,
        (const float4*)W2,
        embh, wqh, wkh, wvh, w0h, w1h, w2h);

    // QKV projections — one merged launch, fp16 outputs
    tc_gemm_qkv<<<dim3(24, MM / 128), blk, GSMEM>>>(
        embh, wqh, wkh, wvh, bq, bk, bv, qh, kh, vh);

    // V transpose (fp16) for the PV mma
    transpose_v<<<dim3(SS / 32, DD / 32, BB), dim3(32, 8)>>>(vh, vth);

    // attention -> zh (fp16, concat-head layout)
    attn_mma<<<dim3(SS / 64, HH, BB), dim3(128), ASMEM>>>(qh, kh, vth, zh);

    // W0 projection + residual(emb) -> t (fp32), then LN1 -> o1 / o1h
    tc_gemm<0, 1, 0><<<dim3(8, 32), blk, GSMEM>>>(
        zh, w0h, b0, emb, t, nullptr, MM, DD, DD);
    ln_kernel<<<MM, blk>>>(t, g1, be1, o1, o1h);

    // FFN
    tc_gemm<1, 0, 1><<<dim3(32, 32), blk, GSMEM>>>(
        o1h, w1h, b1, nullptr, nullptr, hh, MM, FF, DD);
    tc_gemm<0, 1, 0><<<dim3(8, 32), blk, GSMEM>>>(
        hh, w2h, b2, o1, t, nullptr, MM, DD, FF);
    ln_kernel<<<MM, blk>>>(t, g2, be2, out, nullptr);
}